// round 15
// baseline (speedup 1.0000x reference)
#include <cuda_runtime.h>
#include <cuda_bf16.h>
#include <math.h>
#include <stdint.h>

#define B 64
#define S 1024
#define D 768
#define T 4
#define E 8
#define TOPK 2
#define H 3072
#define NH 12
#define HD 64
#define NT 48          // NH*T
#define NTOK 256       // B*T
#define NPAIR 512      // NTOK*TOPK

// ---------------- packed f32x2 helpers (FFMA2) ------------------------------
typedef unsigned long long f32x2;
__device__ __forceinline__ void fma2(f32x2& c, f32x2 a, f32x2 b) {
    asm("fma.rn.f32x2 %0,%1,%2,%0;" : "+l"(c) : "l"(a), "l"(b));
}
__device__ __forceinline__ float2 unpk(f32x2 v) {
    float2 r; asm("mov.b64 {%0,%1},%2;" : "=f"(r.x), "=f"(r.y) : "l"(v)); return r;
}
__device__ __forceinline__ f32x2 dup2(float v) {
    f32x2 r; asm("mov.b64 %0,{%1,%1};" : "=l"(r) : "f"(v)); return r;
}

// ---------------- cp.async helpers -----------------------------------------
__device__ __forceinline__ uint32_t sptr(const void* p) {
    return (uint32_t)__cvta_generic_to_shared(p);
}
__device__ __forceinline__ void cpa16(uint32_t dst, const void* src) {
    asm volatile("cp.async.ca.shared.global [%0], [%1], 16;" :: "r"(dst), "l"(src));
}
__device__ __forceinline__ void cpa16z(uint32_t dst, const void* src, int sz) {
    asm volatile("cp.async.ca.shared.global [%0], [%1], 16, %2;" :: "r"(dst), "l"(src), "r"(sz));
}
#define CPCOMMIT() asm volatile("cp.async.commit_group;")
#define CPWAIT0()  asm volatile("cp.async.wait_group 0;")

// ---------------- warp MMA helpers (HMMA path, plain sm_103-safe) ----------
__device__ __forceinline__ void ldsm4(uint32_t* r, uint32_t addr) {
    asm volatile("ldmatrix.sync.aligned.m8n8.x4.shared.b16 {%0,%1,%2,%3}, [%4];"
        : "=r"(r[0]), "=r"(r[1]), "=r"(r[2]), "=r"(r[3]) : "r"(addr));
}
__device__ __forceinline__ void mma_bf16(float* c, const uint32_t* a, uint32_t b0, uint32_t b1) {
    asm volatile("mma.sync.aligned.m16n8k16.row.col.f32.bf16.bf16.f32 "
        "{%0,%1,%2,%3},{%4,%5,%6,%7},{%8,%9},{%0,%1,%2,%3};"
        : "+f"(c[0]), "+f"(c[1]), "+f"(c[2]), "+f"(c[3])
        : "r"(a[0]), "r"(a[1]), "r"(a[2]), "r"(a[3]), "r"(b0), "r"(b1));
}
// bf16 split helpers
__device__ __forceinline__ uint32_t cvt_bf2(float hi_elem, float lo_elem) {
    uint32_t r; asm("cvt.rn.bf16x2.f32 %0, %1, %2;" : "=r"(r) : "f"(hi_elem), "f"(lo_elem));
    return r;
}
__device__ __forceinline__ float bflo_f(uint32_t w) { return __uint_as_float(w << 16); }
__device__ __forceinline__ float bfhi_f(uint32_t w) { return __uint_as_float(w & 0xffff0000u); }

// split 16 fp32 -> bf16 hi/lo, store 2x uint4 to each of H and L at off
__device__ __forceinline__ void split16(uint8_t* Hb, uint8_t* Lb, int off,
    float4 v0, float4 v1, float4 v2, float4 v3)
{
    uint32_t h0 = cvt_bf2(v0.y, v0.x), h1 = cvt_bf2(v0.w, v0.z);
    uint32_t h2 = cvt_bf2(v1.y, v1.x), h3 = cvt_bf2(v1.w, v1.z);
    uint32_t h4 = cvt_bf2(v2.y, v2.x), h5 = cvt_bf2(v2.w, v2.z);
    uint32_t h6 = cvt_bf2(v3.y, v3.x), h7 = cvt_bf2(v3.w, v3.z);
    uint32_t l0 = cvt_bf2(v0.y - bfhi_f(h0), v0.x - bflo_f(h0));
    uint32_t l1 = cvt_bf2(v0.w - bfhi_f(h1), v0.z - bflo_f(h1));
    uint32_t l2 = cvt_bf2(v1.y - bfhi_f(h2), v1.x - bflo_f(h2));
    uint32_t l3 = cvt_bf2(v1.w - bfhi_f(h3), v1.z - bflo_f(h3));
    uint32_t l4 = cvt_bf2(v2.y - bfhi_f(h4), v2.x - bflo_f(h4));
    uint32_t l5 = cvt_bf2(v2.w - bfhi_f(h5), v2.z - bflo_f(h5));
    uint32_t l6 = cvt_bf2(v3.y - bfhi_f(h6), v3.x - bflo_f(h6));
    uint32_t l7 = cvt_bf2(v3.w - bfhi_f(h7), v3.z - bflo_f(h7));
    *(uint4*)(Hb + off)      = make_uint4(h0, h1, h2, h3);
    *(uint4*)(Hb + off + 16) = make_uint4(h4, h5, h6, h7);
    *(uint4*)(Lb + off)      = make_uint4(l0, l1, l2, l3);
    *(uint4*)(Lb + off + 16) = make_uint4(l4, l5, l6, l7);
}
// split 8 fp32 -> one uint4 each
__device__ __forceinline__ void split8(uint8_t* Hb, uint8_t* Lb, int off,
    float4 v0, float4 v1)
{
    uint32_t h0 = cvt_bf2(v0.y, v0.x), h1 = cvt_bf2(v0.w, v0.z);
    uint32_t h2 = cvt_bf2(v1.y, v1.x), h3 = cvt_bf2(v1.w, v1.z);
    uint32_t l0 = cvt_bf2(v0.y - bfhi_f(h0), v0.x - bflo_f(h0));
    uint32_t l1 = cvt_bf2(v0.w - bfhi_f(h1), v0.z - bflo_f(h1));
    uint32_t l2 = cvt_bf2(v1.y - bfhi_f(h2), v1.x - bflo_f(h2));
    uint32_t l3 = cvt_bf2(v1.w - bfhi_f(h3), v1.z - bflo_f(h3));
    *(uint4*)(Hb + off) = make_uint4(h0, h1, h2, h3);
    *(uint4*)(Lb + off) = make_uint4(l0, l1, l2, l3);
}

// ------------------------- scratch (device globals) -------------------------
__device__ __align__(16) __nv_bfloat16 g_qth[NT * D];
__device__ __align__(16) __nv_bfloat16 g_qtl[NT * D];
__device__ float g_qb[NT];
__device__ __align__(16) float g_scores[(size_t)B * NT * S];          // raw scores (kB->kC)
__device__ __align__(16) __nv_bfloat16 g_ath[(size_t)B * NT * S];     // attn hi (kC->kD)
__device__ __align__(16) __nv_bfloat16 g_atl[(size_t)B * NT * S];     // attn lo
__device__ __align__(16) float g_pooled[(size_t)B * NT * D];
__device__ __align__(16) float g_ctx[NTOK * D];
__device__ __align__(16) float g_ao[NTOK * D];
__device__ __align__(16) __nv_bfloat16 g_xlh[NTOK * D];
__device__ __align__(16) __nv_bfloat16 g_xll[NTOK * D];
__device__ __align__(16) __nv_bfloat16 g_hh[(size_t)NPAIR * H];
__device__ __align__(16) __nv_bfloat16 g_hl[(size_t)NPAIR * H];
__device__ float g_probs[NTOK * E];
__device__ int   g_topi[NTOK * TOPK];
__device__ float g_topw[NTOK * TOPK];
__device__ int   g_ecnt[E];
__device__ int   g_elist[E * NPAIR];
__device__ __align__(16) float g_y[(size_t)NPAIR * D];

__device__ __forceinline__ float wred(float v) {
#pragma unroll
    for (int o = 16; o > 0; o >>= 1) v += __shfl_down_sync(0xffffffffu, v, o);
    return v;
}
__device__ __forceinline__ float wredmax(float v) {
#pragma unroll
    for (int o = 16; o > 0; o >>= 1) v = fmaxf(v, __shfl_down_sync(0xffffffffu, v, o));
    return v;
}
__device__ __forceinline__ int wredi(int v) {
#pragma unroll
    for (int o = 16; o > 0; o >>= 1) v += __shfl_down_sync(0xffffffffu, v, o);
    return v;
}
__device__ __forceinline__ float gelu_tanh(float x) {
    return 0.5f * x * (1.f + tanhf(0.7978845608028654f * (x + 0.044715f * x * x * x)));
}

// ------------------------- kA: qtilde = (probe@Wq^T + bq) @ Wk --------------
__global__ __launch_bounds__(256) void kA_qtilde(
    const float* __restrict__ probe, const float* __restrict__ ipw,
    const float* __restrict__ ipb)
{
    int ht = blockIdx.x;
    int h = ht >> 2, t = ht & 3;
    __shared__ float q_s[HD];
    int tid = threadIdx.x, lane = tid & 31, warp = tid >> 5;

    for (int j = warp; j < HD; j += 8) {
        int row = h * HD + j;
        const float* w = ipw + (size_t)row * D;
        const float* p = probe + t * D;
        float acc = 0.f;
        for (int dd = lane; dd < D; dd += 32) acc += p[dd] * w[dd];
        acc = wred(acc);
        if (lane == 0) q_s[j] = acc + ipb[row];
    }
    __syncthreads();
    if (tid == 0) {
        float qb = 0.f;
        for (int j = 0; j < HD; j++) qb += q_s[j] * ipb[D + h * HD + j];
        g_qb[ht] = qb;
    }
    for (int dd = tid; dd < D; dd += 256) {
        float acc = 0.f;
        const float* wk = ipw + (size_t)(D + h * HD) * D + dd;
#pragma unroll 8
        for (int j = 0; j < HD; j++) acc += q_s[j] * wk[(size_t)j * D];
        __nv_bfloat16 hb = __float2bfloat16(acc);
        float hf = __bfloat162float(hb);
        g_qth[ht * D + dd] = hb;
        g_qtl[ht * D + dd] = __float2bfloat16(acc - hf);
    }
}

// ------------------------- kB: scores, double-buffered, 3 CTAs/SM -----------
// dyn smem layout: AH 0 (2x10240) | AL 20480 | BH 40960 (2x3840) | BL 48640 | qbs 56320
#define KB_SMEM 56512
__global__ __launch_bounds__(256, 3) void kB_scores_mma(const float* __restrict__ hidden)
{
    extern __shared__ __align__(16) uint8_t dsm[];
    uint8_t* AH = dsm;
    uint8_t* AL = dsm + 20480;
    float* qbs = (float*)(dsm + 56320);
    uint32_t base = sptr(dsm);
    uint32_t ah_s = base, bh_s = base + 40960, bl_s = base + 48640;

    int b = blockIdx.y;
    int s0 = blockIdx.x * 128;
    int tid = threadIdx.x, lane = tid & 31, wid = tid >> 5;

    if (tid < NT) qbs[tid] = g_qb[tid];

    int arow = tid & 127, ahalf = tid >> 7;
    const float* hrow = hidden + ((size_t)b * S + s0 + arow) * D + ahalf * 16;
    int aoff = arow * 80 + ahalf * 32;
    int brow = tid >> 2, bu = tid & 3;
    uint32_t boff = (uint32_t)(brow * 80 + bu * 16);

    float4 pv0 = *(const float4*)(hrow + 0);
    float4 pv1 = *(const float4*)(hrow + 4);

    float acc[6][4];
#pragma unroll
    for (int i = 0; i < 6; i++) { acc[i][0] = acc[i][1] = acc[i][2] = acc[i][3] = 0.f; }

    uint32_t a_addr = ah_s + (uint32_t)((wid * 16 + (lane & 15)) * 80 + (lane >> 4) * 16);
    int bmi = lane >> 3;
    uint32_t b_off = (uint32_t)(((bmi >> 1) * 8 + (lane & 7)) * 80 + (bmi & 1) * 16);

    // prologue: stage chunk 0 into buf0, prefetch chunk1 regs (half)
    if (tid < 192) {
        cpa16(bh_s + boff, g_qth + (size_t)brow * D + bu * 8);
        cpa16(bl_s + boff, g_qtl + (size_t)brow * D + bu * 8);
    }
    CPCOMMIT();
    {
        float4 q2 = *(const float4*)(hrow + 8);
        float4 q3 = *(const float4*)(hrow + 12);
        split16(AH, AL, aoff, pv0, pv1, q2, q3);
    }
    pv0 = *(const float4*)(hrow + 32);
    pv1 = *(const float4*)(hrow + 36);
    CPWAIT0();
    __syncthreads();

    const int NCH = D / 32;   // 24
    for (int ch = 0; ch < NCH; ch++) {
        int cur = ch & 1, nxt = cur ^ 1;
        if (ch + 1 < NCH) {
            int k1 = (ch + 1) * 32;
            if (tid < 192) {
                cpa16(bh_s + (uint32_t)(nxt * 3840) + boff, g_qth + (size_t)brow * D + k1 + bu * 8);
                cpa16(bl_s + (uint32_t)(nxt * 3840) + boff, g_qtl + (size_t)brow * D + k1 + bu * 8);
            }
            CPCOMMIT();
        }
#pragma unroll
        for (int ks = 0; ks < 2; ks++) {
            uint32_t ahf[4], alf[4];
            ldsm4(ahf, a_addr + (uint32_t)(cur * 10240) + ks * 32);
            ldsm4(alf, a_addr + 20480u + (uint32_t)(cur * 10240) + ks * 32);
#pragma unroll
            for (int j = 0; j < 3; j++) {
                uint32_t bhf[4], blf[4];
                uint32_t badd = (uint32_t)(cur * 3840 + j * 16 * 80 + ks * 32) + b_off;
                ldsm4(bhf, bh_s + badd);
                ldsm4(blf, bl_s + badd);
                mma_bf16(acc[2 * j], ahf, bhf[0], bhf[1]);
                mma_bf16(acc[2 * j], ahf, blf[0], blf[1]);
                mma_bf16(acc[2 * j], alf, bhf[0], bhf[1]);
                mma_bf16(acc[2 * j + 1], ahf, bhf[2], bhf[3]);
                mma_bf16(acc[2 * j + 1], ahf, blf[2], blf[3]);
                mma_bf16(acc[2 * j + 1], alf, bhf[2], bhf[3]);
            }
        }
        if (ch + 1 < NCH) {
            int k1 = (ch + 1) * 32;
            {
                float4 q2 = *(const float4*)(hrow + k1 + 8);
                float4 q3 = *(const float4*)(hrow + k1 + 12);
                split16(AH + nxt * 10240, AL + nxt * 10240, aoff, pv0, pv1, q2, q3);
            }
            if (ch + 2 < NCH) {
                int k2 = (ch + 2) * 32;
                pv0 = *(const float4*)(hrow + k2);
                pv1 = *(const float4*)(hrow + k2 + 4);
            }
            CPWAIT0();
        }
        __syncthreads();
    }
    int g = lane >> 2, t4 = lane & 3;
    int srow = s0 + wid * 16 + g;
    float* outb = g_scores + (size_t)b * NT * S;
#pragma unroll
    for (int nf = 0; nf < 6; nf++) {
        int n0 = nf * 8 + t4 * 2;
        outb[(size_t)n0 * S + srow]           = 0.125f * (acc[nf][0] + qbs[n0]);
        outb[(size_t)(n0 + 1) * S + srow]     = 0.125f * (acc[nf][1] + qbs[n0 + 1]);
        outb[(size_t)n0 * S + srow + 8]       = 0.125f * (acc[nf][2] + qbs[n0]);
        outb[(size_t)(n0 + 1) * S + srow + 8] = 0.125f * (acc[nf][3] + qbs[n0 + 1]);
    }
}

// ------------------------- kC: softmax + head-mean; write attn bf16 hi/lo ---
__global__ __launch_bounds__(384) void kC_softmax(float* __restrict__ out_aw)
{
    int bt = blockIdx.x, b = bt >> 2, t = bt & 3;
    __shared__ float stage[NH][S];
    int tid = threadIdx.x, lane = tid & 31, warp = tid >> 5;

    size_t rowoff = ((size_t)b * NT + warp * T + t) * S;
    const float* row = g_scores + rowoff;
    float4 v[8];
#pragma unroll
    for (int i = 0; i < 8; i++) v[i] = *(const float4*)(row + i * 128 + lane * 4);
    float m = -1e30f;
#pragma unroll
    for (int i = 0; i < 8; i++)
        m = fmaxf(m, fmaxf(fmaxf(v[i].x, v[i].y), fmaxf(v[i].z, v[i].w)));
    m = wredmax(m);
    m = __shfl_sync(0xffffffffu, m, 0);
    float sum = 0.f;
#pragma unroll
    for (int i = 0; i < 8; i++) {
        v[i].x = __expf(v[i].x - m); v[i].y = __expf(v[i].y - m);
        v[i].z = __expf(v[i].z - m); v[i].w = __expf(v[i].w - m);
        sum += v[i].x + v[i].y + v[i].z + v[i].w;
    }
    sum = wred(sum);
    float inv = 1.f / __shfl_sync(0xffffffffu, sum, 0);
#pragma unroll
    for (int i = 0; i < 8; i++) {
        v[i].x *= inv; v[i].y *= inv; v[i].z *= inv; v[i].w *= inv;
        *(float4*)&stage[warp][i * 128 + lane * 4] = v[i];
        // write attn pre-split bf16 hi/lo (for kD's cp.async A path)
        uint32_t h0 = cvt_bf2(v[i].y, v[i].x), h1 = cvt_bf2(v[i].w, v[i].z);
        uint32_t l0 = cvt_bf2(v[i].y - bfhi_f(h0), v[i].x - bflo_f(h0));
        uint32_t l1 = cvt_bf2(v[i].w - bfhi_f(h1), v[i].z - bflo_f(h1));
        size_t idx = rowoff + i * 128 + lane * 4;
        *(uint2*)&g_ath[idx] = make_uint2(h0, h1);
        *(uint2*)&g_atl[idx] = make_uint2(l0, l1);
    }
    __syncthreads();
    const float inv12 = 1.f / 12.f;
#pragma unroll
    for (int r = 0; r < 3; r++) {
        int s = tid + 384 * r;
        if (s < S) {
            float a = 0.f;
#pragma unroll
            for (int h = 0; h < NH; h++) a += stage[h][s];
            out_aw[(size_t)bt * S + s] = a * inv12;
        }
    }
}

// ------------------------- kD: pooled, cp.async A, 3 CTAs/SM ----------------
// dyn smem: AH 0 (2x3840) | AL 7680 | BH 15360 (2x10240) | BL 35840 ; total 56320
#define KD_SMEM 56320
__global__ __launch_bounds__(256, 3) void kD_pooled_mma(const float* __restrict__ hidden)
{
    extern __shared__ __align__(16) uint8_t dsm[];
    uint8_t* BH = dsm + 15360;
    uint8_t* BL = dsm + 35840;
    uint32_t base = sptr(dsm);
    uint32_t ah_s = base, al_s = base + 7680, bh_s = base + 15360, bl_s = base + 35840;

    int b = blockIdx.y;
    int n0 = blockIdx.x * 128;
    int tid = threadIdx.x, lane = tid & 31, wid = tid >> 5;

    // A loader (tid<192): pre-split attn via cp.async
    int am = tid >> 2, au = tid & 3;
    size_t arowo = ((size_t)b * NT + (am < NT ? am : 0)) * S + au * 8;
    uint32_t a_stoff = (uint32_t)(am * 80 + au * 16);

    // B loader: thread owns column n (128), k-half bkg (16 k each)
    int bn = tid & 127, bkg = tid >> 7;
    const float* hcol = hidden + ((size_t)b * S + bkg * 16) * D + n0 + bn;
    int b_st = bn * 80 + bkg * 32;

    float hb0[8];
#pragma unroll
    for (int j = 0; j < 8; j++) hb0[j] = hcol[(size_t)j * D];

    float acc[3][2][4];
#pragma unroll
    for (int i = 0; i < 3; i++)
#pragma unroll
        for (int f = 0; f < 2; f++) { acc[i][f][0] = acc[i][f][1] = acc[i][f][2] = acc[i][f][3] = 0.f; }

    uint32_t aA[3];
#pragma unroll
    for (int st = 0; st < 3; st++)
        aA[st] = ah_s + (uint32_t)((st * 16 + (lane & 15)) * 80 + (lane >> 4) * 16);
    int bmi = lane >> 3;
    uint32_t b_off = (uint32_t)((wid * 16 + (bmi >> 1) * 8 + (lane & 7)) * 80 + (bmi & 1) * 16);

    // prologue: A chunk0 cp.async; B chunk0 stage; prefetch chunk1 B half
    if (tid < 192) {
        cpa16(ah_s + a_stoff, g_ath + arowo);
        cpa16(al_s + a_stoff, g_atl + arowo);
    }
    CPCOMMIT();
    split8(dsm + 15360, dsm + 35840, b_st,
           make_float4(hb0[0], hb0[1], hb0[2], hb0[3]),
           make_float4(hb0[4], hb0[5], hb0[6], hb0[7]));
    {
        float4 q0 = make_float4(hcol[8 * (size_t)D], hcol[9 * (size_t)D], hcol[10 * (size_t)D], hcol[11 * (size_t)D]);
        float4 q1 = make_float4(hcol[12 * (size_t)D], hcol[13 * (size_t)D], hcol[14 * (size_t)D], hcol[15 * (size_t)D]);
        split8(BH, BL, b_st + 16, q0, q1);
    }
#pragma unroll
    for (int j = 0; j < 8; j++) hb0[j] = hcol[(size_t)(32 + j) * D];
    CPWAIT0();
    __syncthreads();

    const int NCH = S / 32;   // 32
    for (int ch = 0; ch < NCH; ch++) {
        int cur = ch & 1, nxt = cur ^ 1;
        if (ch + 1 < NCH) {
            int k1 = (ch + 1) * 32;
            if (tid < 192) {
                cpa16(ah_s + (uint32_t)(nxt * 3840) + a_stoff, g_ath + arowo + k1);
                cpa16(al_s + (uint32_t)(nxt * 3840) + a_stoff, g_atl + arowo + k1);
            }
            CPCOMMIT();
        }
#pragma unroll
        for (int ks = 0; ks < 2; ks++) {
            uint32_t bhf[4], blf[4];
            ldsm4(bhf, bh_s + (uint32_t)(cur * 10240) + b_off + ks * 32);
            ldsm4(blf, bl_s + (uint32_t)(cur * 10240) + b_off + ks * 32);
#pragma unroll
            for (int st = 0; st < 3; st++) {
                uint32_t ahf[4], alf[4];
                uint32_t aadd = aA[st] + (uint32_t)(cur * 3840) + ks * 32;
                ldsm4(ahf, aadd);
                ldsm4(alf, aadd + 7680u);
                mma_bf16(acc[st][0], ahf, bhf[0], bhf[1]);
                mma_bf16(acc[st][0], ahf, blf[0], blf[1]);
                mma_bf16(acc[st][0], alf, bhf[0], bhf[1]);
                mma_bf16(acc[st][1], ahf, bhf[2], bhf[3]);
                mma_bf16(acc[st][1], ahf, blf[2], blf[3]);
                mma_bf16(acc[st][1], alf, bhf[2], bhf[3]);
            }
        }
        if (ch + 1 < NCH) {
            int k1 = (ch + 1) * 32;
            split8(BH + nxt * 10240, BL + nxt * 10240, b_st,
                   make_float4(hb0[0], hb0[1], hb0[2], hb0[3]),
                   make_float4(hb0[4], hb0[5], hb0[6], hb0[7]));
            {
                const float* hc = hcol + (size_t)k1 * D;
                float4 q0 = make_float4(hc[8 * (size_t)D], hc[9 * (size_t)D], hc[10 * (size_t)D], hc[11 * (size_t)D]);
                float4 q1 = make_float4(hc[12 * (size_t)D], hc[13 * (size_t)D], hc[14 * (size_t)D], hc[15 * (size_t)D]);
                split8(BH + nxt * 10240, BL + nxt * 10240, b_st + 16, q0, q1);
            }
            if (ch + 2 < NCH) {
                int k2 = (ch + 2) * 32;
                const float* hc2 = hcol + (size_t)k2 * D;
#pragma unroll
                for (int j = 0; j < 8; j++) hb0[j] = hc2[(size_t)j * D];
            }
            CPWAIT0();
        }
        __syncthreads();
    }
    int g = lane >> 2, t4 = lane & 3;
#pragma unroll
    for (int st = 0; st < 3; st++) {
        int m = st * 16 + g;
        float* base0 = g_pooled + ((size_t)b * NT + m) * D + n0;
        float* base1 = g_pooled + ((size_t)b * NT + m + 8) * D + n0;
#pragma unroll
        for (int f = 0; f < 2; f++) {
            int n = wid * 16 + f * 8 + t4 * 2;
            base0[n]     = acc[st][f][0];
            base0[n + 1] = acc[st][f][1];
            base1[n]     = acc[st][f][2];
            base1[n + 1] = acc[st][f][3];
        }
    }
}

// ------------------------- kE1: v-proj via mma.sync bf16-split --------------
__global__ __launch_bounds__(256, 2) void kE1_vproj_mma(
    const float* __restrict__ ipw, const float* __restrict__ ipb)
{
    __shared__ __align__(16) uint8_t AH[64 * 80];
    __shared__ __align__(16) uint8_t AL[64 * 80];
    __shared__ __align__(16) uint8_t BH[64 * 80];
    __shared__ __align__(16) uint8_t BL[64 * 80];

    int h = blockIdx.x;
    int tok0 = blockIdx.y * 64;
    int tid = threadIdx.x, lane = tid & 31, wid = tid >> 5;
    int st = wid & 3, nh = wid >> 2;

    uint32_t ah_s = sptr(AH), al_s = sptr(AL), bh_s = sptr(BH), bl_s = sptr(BL);

    int arow = tid >> 2, aq = tid & 3;
    const float* wrow = ipw + (size_t)(2 * D + h * HD + arow) * D + aq * 8;
    int tk = tok0 + (tid >> 2);
    const float* prow = g_pooled + ((size_t)(tk >> 2) * NT + h * T + (tk & 3)) * D + aq * 8;

    float4 pa0 = *(const float4*)wrow, pa1 = *(const float4*)(wrow + 4);
    float4 pb0 = *(const float4*)prow, pb1 = *(const float4*)(prow + 4);

    float acc[4][4];
#pragma unroll
    for (int i = 0; i < 4; i++) { acc[i][0] = acc[i][1] = acc[i][2] = acc[i][3] = 0.f; }

    uint32_t a_addr = ah_s + (uint32_t)((st * 16 + (lane & 15)) * 80 + (lane >> 4) * 16);
    uint32_t al_addr = a_addr + (al_s - ah_s);
    int bmi = lane >> 3;
    uint32_t b_off = (uint32_t)((nh * 32 + (bmi >> 1) * 8 + (lane & 7)) * 80 + (bmi & 1) * 16);

    const int NCH = D / 32;
    for (int ch = 0; ch < NCH; ch++) {
        {
            int off = arow * 80 + aq * 16;
            split8(AH, AL, off, pa0, pa1);
            split8(BH, BL, off, pb0, pb1);
        }
        __syncthreads();
        if (ch + 1 < NCH) {
            int k1 = (ch + 1) * 32;
            pa0 = *(const float4*)(wrow + k1);
            pa1 = *(const float4*)(wrow + k1 + 4);
            pb0 = *(const float4*)(prow + k1);
            pb1 = *(const float4*)(prow + k1 + 4);
        }
#pragma unroll
        for (int ks = 0; ks < 2; ks++) {
            uint32_t ahf[4], alf[4];
            ldsm4(ahf, a_addr + ks * 32);
            ldsm4(alf, al_addr + ks * 32);
#pragma unroll
            for (int j = 0; j < 2; j++) {
                uint32_t bhf[4], blf[4];
                uint32_t badd = (uint32_t)(j * 16 * 80 + ks * 32) + b_off;
                ldsm4(bhf, bh_s + badd);
                ldsm4(blf, bl_s + badd);
                mma_bf16(acc[2 * j], ahf, bhf[0], bhf[1]);
                mma_bf16(acc[2 * j], ahf, blf[0], blf[1]);
                mma_bf16(acc[2 * j], alf, bhf[0], bhf[1]);
                mma_bf16(acc[2 * j + 1], ahf, bhf[2], bhf[3]);
                mma_bf16(acc[2 * j + 1], ahf, blf[2], blf[3]);
                mma_bf16(acc[2 * j + 1], alf, bhf[2], bhf[3]);
            }
        }
        __syncthreads();
    }
    int g = lane >> 2, t4 = lane & 3;
    int jA = h * HD + st * 16 + g;
    int jB = jA + 8;
    float bA = ipb[2 * D + jA], bB = ipb[2 * D + jB];
#pragma unroll
    for (int nf = 0; nf < 4; nf++) {
        int tkc = tok0 + nh * 32 + nf * 8 + t4 * 2;
        g_ctx[(size_t)tkc * D + jA]       = acc[nf][0] + bA;
        g_ctx[(size_t)(tkc + 1) * D + jA] = acc[nf][1] + bA;
        g_ctx[(size_t)tkc * D + jB]       = acc[nf][2] + bB;
        g_ctx[(size_t)(tkc + 1) * D + jB] = acc[nf][3] + bB;
    }
}

// ------------------------- kE2: out-proj GEMM + residual --------------------
__global__ __launch_bounds__(256) void kE2_outproj(
    const float* __restrict__ opw, const float* __restrict__ opb,
    float* __restrict__ out_y)
{
    int r0 = blockIdx.x * 128;
    int t0 = blockIdx.y * 32;
    __shared__ __align__(16) float cs[32 * 17];
    __shared__ __align__(16) float ws[16 * 132 + 16];
    int tid = threadIdx.x;
    int tr = tid & 31;
    int tt = tid >> 5;
    f32x2 acc[4][2];
#pragma unroll
    for (int t = 0; t < 4; t++) { acc[t][0] = 0ull; acc[t][1] = 0ull; }

    for (int k0 = 0; k0 < D; k0 += 16) {
#pragma unroll
        for (int r = 0; r < 2; r++) {
            int idx = tid + 256 * r;
            int tok = idx >> 4, kk = idx & 15;
            cs[tok * 17 + kk] = g_ctx[(size_t)(t0 + tok) * D + k0 + kk];
        }
#pragma unroll
        for (int r = 0; r < 2; r++) {
            int idx = tid + 256 * r;
            int rr = idx >> 2, ko = (idx & 3) << 2;
            float4 v = *(const float4*)(opw + (size_t)(r0 + rr) * D + k0 + ko);
            float* base = &ws[ko * 132 + rr + ko];
            base[0] = v.x; base[132] = v.y; base[264] = v.z; base[396] = v.w;
        }
        __syncthreads();
#pragma unroll 4
        for (int kk = 0; kk < 16; kk++) {
            ulonglong2 wu = *(const ulonglong2*)(&ws[kk * 132 + (kk & 12)] + tr * 4);
#pragma unroll
            for (int t = 0; t < 4; t++) {
                f32x2 ad = dup2(cs[(tt * 4 + t) * 17 + kk]);
                fma2(acc[t][0], wu.x, ad);
                fma2(acc[t][1], wu.y, ad);
            }
        }
        __syncthreads();
    }
    float4 bb = *(const float4*)&opb[r0 + tr * 4];
#pragma unroll
    for (int t = 0; t < 4; t++) {
        int tok = t0 + tt * 4 + t;
        float2 u0 = unpk(acc[t][0]), u1 = unpk(acc[t][1]);
        float4 o = make_float4(u0.x + bb.x, u0.y + bb.y, u1.x + bb.z, u1.y + bb.w);
        *(float4*)&out_y[(size_t)tok * D + r0 + tr * 4] = o;
        *(float4*)&g_ao[(size_t)tok * D + r0 + tr * 4] = o;
    }
}

// ------------------------- kE3: LN + gate + top2, per token -----------------
__global__ __launch_bounds__(256) void kE3_ln_gate(
    const float* __restrict__ lnw, const float* __restrict__ lnb,
    const float* __restrict__ gw)
{
    int tok = blockIdx.x;
    int t = tok & 3;
    __shared__ float x[D];
    __shared__ float red[256];
    __shared__ float lg[E];
    int tid = threadIdx.x, lane = tid & 31, warp = tid >> 5;

    float v0 = g_ao[(size_t)tok * D + tid];
    float v1 = g_ao[(size_t)tok * D + tid + 256];
    float v2 = g_ao[(size_t)tok * D + tid + 512];
    red[tid] = v0 + v1 + v2; __syncthreads();
    for (int o = 128; o > 0; o >>= 1) { if (tid < o) red[tid] += red[tid + o]; __syncthreads(); }
    float mu = red[0] * (1.f / 768.f); __syncthreads();
    float d0 = v0 - mu, d1 = v1 - mu, d2 = v2 - mu;
    red[tid] = d0 * d0 + d1 * d1 + d2 * d2; __syncthreads();
    for (int o = 128; o > 0; o >>= 1) { if (tid < o) red[tid] += red[tid + o]; __syncthreads(); }
    float rstd = rsqrtf(red[0] * (1.f / 768.f) + 1e-6f); __syncthreads();

#pragma unroll
    for (int r = 0; r < 3; r++) {
        int dd = tid + 256 * r;
        float dv = (r == 0) ? d0 : (r == 1) ? d1 : d2;
        float xv = dv * rstd * lnw[dd] + lnb[dd];
        x[dd] = xv;
        __nv_bfloat16 hb = __float2bfloat16(xv);
        g_xlh[(size_t)tok * D + dd] = hb;
        g_xll[(size_t)tok * D + dd] = __float2bfloat16(xv - __bfloat162float(hb));
    }
    __syncthreads();

    if (warp < E) {
        float acc = 0.f;
        for (int dd = lane; dd < D; dd += 32)
            acc += x[dd] * gw[((size_t)t * D + dd) * E + warp];
        acc = wred(acc);
        if (lane == 0) lg[warp] = acc;
    }
    __syncthreads();
    if (tid == 0) {
        float p[E];
        float mx = lg[0];
        for (int e = 1; e < E; e++) mx = fmaxf(mx, lg[e]);
        float sum = 0.f;
        for (int e = 0; e < E; e++) { p[e] = __expf(lg[e] - mx); sum += p[e]; }
        float inv = 1.f / sum;
        for (int e = 0; e < E; e++) { p[e] *= inv; g_probs[tok * E + e] = p[e]; }
        int i0 = 0;
        for (int e = 1; e < E; e++) if (p[e] > p[i0]) i0 = e;
        int i1 = (i0 == 0) ? 1 : 0;
        for (int e = 0; e < E; e++) if (e != i0 && p[e] > p[i1]) i1 = e;
        float inv2 = 1.f / (p[i0] + p[i1]);
        g_topi[tok * 2] = i0; g_topi[tok * 2 + 1] = i1;
        g_topw[tok * 2] = p[i0] * inv2; g_topw[tok * 2 + 1] = p[i1] * inv2;
    }
}

// ------------------------- kF: routing lists + moe_loss ---------------------
__global__ __launch_bounds__(256) void kF_route(float* __restrict__ out_loss)
{
    __shared__ int ti[NPAIR];
    __shared__ float imp_s[E];
    __shared__ int disp_s[E];
    int tid = threadIdx.x, lane = tid & 31, warp = tid >> 5;
    for (int i = tid; i < NPAIR; i += 256) ti[i] = g_topi[i];
    __syncthreads();
    if (warp < E) {
        float acc = 0.f;
        for (int tok = lane; tok < NTOK; tok += 32) acc += g_probs[tok * E + warp];
        int cnt = 0;
        for (int p = lane; p < NPAIR; p += 32) cnt += (ti[p] == warp);
        acc = wred(acc); cnt = wredi(cnt);
        if (lane == 0) { imp_s[warp] = acc * (1.f / NTOK); disp_s[warp] = cnt; }
    }
    __syncthreads();
    if (tid == 0) {
        float loss = 0.f;
        for (int e = 0; e < E; e++) loss += imp_s[e] * ((float)disp_s[e] * (1.f / NTOK));
        out_loss[0] = (float)E * loss;
    }
    if (tid < E) {
        int c = 0;
        for (int p = 0; p < NPAIR; p++)
            if (ti[p] == tid) g_elist[tid * NPAIR + (c++)] = p;
        g_ecnt[tid] = c;
    }
}

// ------------------------- kG/kH: MoE GEMMs, double-buffered -----------------
// dyn smem: AH 0 (2x10240) | AL 20480 | BH 40960 (2x5120) | BL 51200 | plist 61440
#define GM_SMEM 61696
#define GM_CH 64
__global__ __launch_bounds__(256, 2) void kG_fc1_mma(
    const float* __restrict__ w1, const float* __restrict__ b1)
{
    extern __shared__ __align__(16) uint8_t dsm[];
    uint8_t* AH = dsm;
    uint8_t* AL = dsm + 20480;
    int* plist = (int*)(dsm + 61440);
    uint32_t base = sptr(dsm);
    uint32_t ah_s = base, bh_s = base + 40960, bl_s = base + 51200;

    int h0 = blockIdx.x * 128;
    int e = blockIdx.y;
    int c0 = blockIdx.z * GM_CH;
    int nt = g_ecnt[e];
    if (c0 >= nt) return;
    int ctn = min(GM_CH, nt - c0);
    int tid = threadIdx.x, lane = tid & 31, wid = tid >> 5;
    if (tid < GM_CH) plist[tid] = (tid < ctn) ? g_elist[e * NPAIR + c0 + tid] : -1;
    __syncthreads();

    int arow = tid & 127, ahalf = tid >> 7;
    const float* wrow = w1 + ((size_t)e * H + h0 + arow) * D + ahalf * 16;
    int aoff = arow * 80 + ahalf * 32;

    int brow = tid >> 2, bu = tid & 3;
    uint32_t boff = (uint32_t)(brow * 80 + bu * 16);
    int bp = plist[brow];
    int bok = (bp >= 0) ? 16 : 0;
    const __nv_bfloat16* xh = g_xlh + ((bp >= 0) ? (size_t)(bp >> 1) * D : 0) + bu * 8;
    const __nv_bfloat16* xl = g_xll + ((bp >= 0) ? (size_t)(bp >> 1) * D : 0) + bu * 8;

    float4 pv0 = *(const float4*)(wrow + 0);
    float4 pv1 = *(const float4*)(wrow + 4);
    float4 pv2 = *(const float4*)(wrow + 8);
    float4 pv3 = *(const float4*)(wrow + 12);

    float acc[8][4];
#pragma unroll
    for (int i = 0; i < 8; i++) { acc[i][0] = acc[i][1] = acc[i][2] = acc[i][3] = 0.f; }

    uint32_t a_addr = ah_s + (uint32_t)((wid * 16 + (lane & 15)) * 80 + (lane >> 4) * 16);
    int bmi = lane >> 3;
    uint32_t b_off = (uint32_t)(((bmi >> 1) * 8 + (lane & 7)) * 80 + (bmi & 1) * 16);

    cpa16z(bh_s + boff, xh, bok);
    cpa16z(bl_s + boff, xl, bok);
    CPCOMMIT();
    split16(AH, AL, aoff, pv0, pv1, pv2, pv3);
    {
        const float* nx = wrow + 32;
        pv0 = *(const float4*)(nx + 0); pv1 = *(const float4*)(nx + 4);
        pv2 = *(const float4*)(nx + 8); pv3 = *(const float4*)(nx + 12);
    }
    CPWAIT0();
    __syncthreads();

    const int NCH = D / 32;   // 24
    for (int ch = 0; ch < NCH; ch++) {
        int cur = ch & 1, nxt = cur ^ 1;
        if (ch + 1 < NCH) {
            int k1 = (ch + 1) * 32;
            cpa16z(bh_s + (uint32_t)(nxt * 5120) + boff, xh + k1, bok);
            cpa16z(bl_s + (uint32_t)(nxt * 5120) + boff, xl + k1, bok);
            CPCOMMIT();
        }
#pragma unroll
        for (int ks = 0; ks < 2; ks++) {
            uint32_t ahf[4], alf[4];
            ldsm4(ahf, a_addr + (uint32_t)(cur * 10240) + ks * 32);
            ldsm4(alf, a_addr + 20480u + (uint32_t)(cur * 10240) + ks * 32);
#pragma unroll
            for (int j = 0; j < 4; j++) {
                uint32_t bhf[4], blf[4];
                uint32_t badd = (uint32_t)(cur * 5120 + j * 16 * 80 + ks * 32) + b_off;
                ldsm4(bhf, bh_s + badd);
                ldsm4(blf, bl_s + badd);
                mma_bf16(acc[2 * j], ahf, bhf[0], bhf[1]);
                mma_bf16(acc[2 * j], ahf, blf[0], blf[1]);
                mma_bf16(acc[2 * j], alf, bhf[0], bhf[1]);
                mma_bf16(acc[2 * j + 1], ahf, bhf[2], bhf[3]);
                mma_bf16(acc[2 * j + 1], ahf, blf[2], blf[3]);
                mma_bf16(acc[2 * j + 1], alf, bhf[2], bhf[3]);
            }
        }
        if (ch + 1 < NCH) {
            split16(AH + nxt * 10240, AL + nxt * 10240, aoff, pv0, pv1, pv2, pv3);
            if (ch + 2 < NCH) {
                const float* nx = wrow + (ch + 2) * 32;
                pv0 = *(const float4*)(nx + 0); pv1 = *(const float4*)(nx + 4);
                pv2 = *(const float4*)(nx + 8); pv3 = *(const float4*)(nx + 12);
            }
            CPWAIT0();
        }
        __syncthreads();
    }
    int g = lane >> 2, t4 = lane & 3;
    int hhA = h0 + wid * 16 + g;
    int hhB = hhA + 8;
    float bA = b1[e * H + hhA], bB = b1[e * H + hhB];
#pragma unroll
    for (int nf = 0; nf < 8; nf++) {
        int tok = nf * 8 + t4 * 2;
        if (tok < ctn) {
            int p = plist[tok];
            float vA = gelu_tanh(acc[nf][0] + bA);
            float vB = gelu_tanh(acc[nf][2] + bB);
            __nv_bfloat16 ha = __float2bfloat16(vA);
            __nv_bfloat16 hb2 = __float2bfloat16(vB);
            g_hh[(size_t)p * H + hhA] = ha;
            g_hl[(size_t)p * H + hhA] = __float2bfloat16(vA - __bfloat162float(ha));
            g_hh[(size_t)p * H + hhB] = hb2;
            g_hl[(size_t)p * H + hhB] = __float2bfloat16(vB - __bfloat162float(hb2));
        }
        if (tok + 1 < ctn) {
            int p = plist[tok + 1];
            float vA = gelu_tanh(acc[nf][1] + bA);
            float vB = gelu_tanh(acc[nf][3] + bB);
            __nv_bfloat16 ha = __float2bfloat16(vA);
            __nv_bfloat16 hb2 = __float2bfloat16(vB);
            g_hh[(size_t)p * H + hhA] = ha;
            g_hl[(size_t)p * H + hhA] = __float2bfloat16(vA - __bfloat162float(ha));
            g_hh[(size_t)p * H + hhB] = hb2;
            g_hl[(size_t)p * H + hhB] = __float2bfloat16(vB - __bfloat162float(hb2));
        }
    }
}

__global__ __launch_bounds__(256, 2) void kH_fc2_mma(
    const float* __restrict__ w2, const float* __restrict__ b2)
{
    extern __shared__ __align__(16) uint8_t dsm[];
    uint8_t* AH = dsm;
    uint8_t* AL = dsm + 20480;
    int* plist = (int*)(dsm + 61440);
    uint32_t base = sptr(dsm);
    uint32_t ah_s = base, bh_s = base + 40960, bl_s = base + 51200;

    int n0 = blockIdx.x * 128;
    int e = blockIdx.y;
    int c0 = blockIdx.z * GM_CH;
    int nt = g_ecnt[e];
    if (c0 >= nt) return;
    int ctn = min(GM_CH, nt - c0);
    int tid = threadIdx.x, lane = tid & 31, wid = tid >> 5;
    if (tid < GM_CH) plist[tid] = (tid < ctn) ? g_elist[e * NPAIR + c0 + tid] : -1;
    __syncthreads();

    int arow = tid & 127, ahalf = tid >> 7;
    const float* wrow = w2 + ((size_t)e * D + n0 + arow) * H + ahalf * 16;
    int aoff = arow * 80 + ahalf * 32;

    int brow = tid >> 2, bu = tid & 3;
    uint32_t boff = (uint32_t)(brow * 80 + bu * 16);
    int bp = plist[brow];
    int bok = (bp >= 0) ? 16 : 0;
    const __nv_bfloat16* xh = g_hh + ((bp >= 0) ? (size_t)bp * H : 0) + bu * 8;
    const __nv_bfloat16* xl = g_hl + ((bp >= 0) ? (size_t)bp * H : 0) + bu * 8;

    float4 pv0 = *(const float4*)(wrow + 0);
    float4 pv1 = *(const float4*)(wrow + 4);
    float4 pv2 = *(const float4*)(wrow + 8);
    float4 pv3 = *(const float4*)(wrow + 12);

    float acc[8][4];
#pragma unroll
    for (int i = 0; i < 8; i++) { acc[i][0] = acc[i][1] = acc[i][2] = acc[i][3] = 0.f; }

    uint32_t a_addr = ah_s + (uint32_t)((wid * 16 + (lane & 15)) * 80 + (lane >> 4) * 16);
    int bmi = lane >> 3;
    uint32_t b_off = (uint32_t)(((bmi >> 1) * 8 + (lane & 7)) * 80 + (bmi & 1) * 16);

    cpa16z(bh_s + boff, xh, bok);
    cpa16z(bl_s + boff, xl, bok);
    CPCOMMIT();
    split16(AH, AL, aoff, pv0, pv1, pv2, pv3);
    {
        const float* nx = wrow + 32;
        pv0 = *(const float4*)(nx + 0); pv1 = *(const float4*)(nx + 4);
        pv2 = *(const float4*)(nx + 8); pv3 = *(const float4*)(nx + 12);
    }
    CPWAIT0();
    __syncthreads();

    const int NCH = H / 32;   // 96
    for (int ch = 0; ch < NCH; ch++) {
        int cur = ch & 1, nxt = cur ^ 1;
        if (ch + 1 < NCH) {
            int k1 = (ch + 1) * 32;
            cpa16z(bh_s + (uint32_t)(nxt * 5120) + boff, xh + k1, bok);
            cpa16z(bl_s + (uint32_t)(nxt * 5120) + boff, xl + k1, bok);
            CPCOMMIT();
        }
#pragma unroll
        for (int ks = 0; ks < 2; ks++) {
            uint32_t ahf[4], alf[4];
            ldsm4(ahf, a_addr + (uint32_t)(cur * 10240) + ks * 32);
            ldsm4(alf, a_addr + 20480u + (uint32_t)(cur * 10240) + ks * 32);
#pragma unroll
            for (int j = 0; j < 4; j++) {
                uint32_t bhf[4], blf[4];
                uint32_t badd = (uint32_t)(cur * 5120 + j * 16 * 80 + ks * 32) + b_off;
                ldsm4(bhf, bh_s + badd);
                ldsm4(blf, bl_s + badd);
                mma_bf16(acc[2 * j], ahf, bhf[0], bhf[1]);
                mma_bf16(acc[2 * j], ahf, blf[0], blf[1]);
                mma_bf16(acc[2 * j], alf, bhf[0], bhf[1]);
                mma_bf16(acc[2 * j + 1], ahf, bhf[2], bhf[3]);
                mma_bf16(acc[2 * j + 1], ahf, blf[2], blf[3]);
                mma_bf16(acc[2 * j + 1], alf, bhf[2], bhf[3]);
            }
        }
        if (ch + 1 < NCH) {
            split16(AH + nxt * 10240, AL + nxt * 10240, aoff, pv0, pv1, pv2, pv3);
            if (ch + 2 < NCH) {
                const float* nx = wrow + (ch + 2) * 32;
                pv0 = *(const float4*)(nx + 0); pv1 = *(const float4*)(nx + 4);
                pv2 = *(const float4*)(nx + 8); pv3 = *(const float4*)(nx + 12);
            }
            CPWAIT0();
        }
        __syncthreads();
    }
    int g = lane >> 2, t4 = lane & 3;
    int ddA = n0 + wid * 16 + g;
    int ddB = ddA + 8;
    float bA = b2[e * D + ddA], bB = b2[e * D + ddB];
#pragma unroll
    for (int nf = 0; nf < 8; nf++) {
        int tok = nf * 8 + t4 * 2;
        if (tok < ctn) {
            int p = plist[tok];
            g_y[(size_t)p * D + ddA] = acc[nf][0] + bA;
            g_y[(size_t)p * D + ddB] = acc[nf][2] + bB;
        }
        if (tok + 1 < ctn) {
            int p = plist[tok + 1];
            g_y[(size_t)p * D + ddA] = acc[nf][1] + bA;
            g_y[(size_t)p * D + ddB] = acc[nf][3] + bB;
        }
    }
}

// ------------------------- kI: combine -------------------------------------
__global__ __launch_bounds__(256) void kI_combine(float* __restrict__ out_y)
{
    int tok = blockIdx.x;
    int tid = threadIdx.x;
    float w0 = g_topw[tok * 2], w1 = g_topw[tok * 2 + 1];
    const float* y0 = &g_y[(size_t)(tok * 2) * D];
    const float* y1 = &g_y[(size_t)(tok * 2 + 1) * D];
    for (int dd = tid; dd < D; dd += 256)
        out_y[(size_t)tok * D + dd] += w0 * y0[dd] + w1 * y1[dd];
}

// ------------------------- launch ------------------------------------------
extern "C" void kernel_launch(void* const* d_in, const int* in_sizes, int n_in,
                              void* d_out, int out_size)
{
    (void)in_sizes; (void)n_in; (void)out_size;
    const float* hidden = (const float*)d_in[0];
    const float* probe  = (const float*)d_in[1];
    const float* ipw    = (const float*)d_in[2];
    const float* ipb    = (const float*)d_in[3];
    const float* opw    = (const float*)d_in[4];
    const float* opb    = (const float*)d_in[5];
    const float* lnw    = (const float*)d_in[6];
    const float* lnb    = (const float*)d_in[7];
    const float* gw     = (const float*)d_in[8];
    const float* w1     = (const float*)d_in[9];
    const float* b1     = (const float*)d_in[10];
    const float* w2     = (const float*)d_in[11];
    const float* b2     = (const float*)d_in[12];
    float* out = (float*)d_out;

    cudaFuncSetAttribute(kB_scores_mma, cudaFuncAttributeMaxDynamicSharedMemorySize, KB_SMEM);
    cudaFuncSetAttribute(kD_pooled_mma, cudaFuncAttributeMaxDynamicSharedMemorySize, KD_SMEM);
    cudaFuncSetAttribute(kG_fc1_mma, cudaFuncAttributeMaxDynamicSharedMemorySize, GM_SMEM);
    cudaFuncSetAttribute(kH_fc2_mma, cudaFuncAttributeMaxDynamicSharedMemorySize, GM_SMEM);

    const int OFF_LOSS = B * T * D;        // 196608
    const int OFF_AW   = OFF_LOSS + 1;     // 196609

    kA_qtilde<<<NT, 256>>>(probe, ipw, ipb);
    kB_scores_mma<<<dim3(S / 128, B), 256, KB_SMEM>>>(hidden);
    kC_softmax<<<NTOK, 384>>>(out + OFF_AW);
    kD_pooled_mma<<<dim3(D / 128, B), 256, KD_SMEM>>>(hidden);
    kE1_vproj_mma<<<dim3(NH, 4), 256>>>(ipw, ipb);
    kE2_outproj<<<dim3(6, 8), 256>>>(opw, opb, out);
    kE3_ln_gate<<<NTOK, 256>>>(lnw, lnb, gw);
    kF_route<<<1, 256>>>(out + OFF_LOSS);
    kG_fc1_mma<<<dim3(H / 128, E, 4), 256, GM_SMEM>>>(w1, b1);
    kH_fc2_mma<<<dim3(D / 128, E, 4), 256, GM_SMEM>>>(w2, b2);
    kI_combine<<<NTOK, 256>>>(out);
}

// round 16
// speedup vs baseline: 1.0258x; 1.0258x over previous
#include <cuda_runtime.h>
#include <cuda_bf16.h>
#include <math.h>
#include <stdint.h>

#define B 64
#define S 1024
#define D 768
#define T 4
#define E 8
#define TOPK 2
#define H 3072
#define NH 12
#define HD 64
#define NT 48          // NH*T
#define NTOK 256       // B*T
#define NPAIR 512      // NTOK*TOPK

// ---------------- packed f32x2 helpers (FFMA2) ------------------------------
typedef unsigned long long f32x2;
__device__ __forceinline__ void fma2(f32x2& c, f32x2 a, f32x2 b) {
    asm("fma.rn.f32x2 %0,%1,%2,%0;" : "+l"(c) : "l"(a), "l"(b));
}
__device__ __forceinline__ float2 unpk(f32x2 v) {
    float2 r; asm("mov.b64 {%0,%1},%2;" : "=f"(r.x), "=f"(r.y) : "l"(v)); return r;
}
__device__ __forceinline__ f32x2 dup2(float v) {
    f32x2 r; asm("mov.b64 %0,{%1,%1};" : "=l"(r) : "f"(v)); return r;
}

// ---------------- cp.async helpers -----------------------------------------
__device__ __forceinline__ uint32_t sptr(const void* p) {
    return (uint32_t)__cvta_generic_to_shared(p);
}
__device__ __forceinline__ void cpa16(uint32_t dst, const void* src) {
    asm volatile("cp.async.ca.shared.global [%0], [%1], 16;" :: "r"(dst), "l"(src));
}
__device__ __forceinline__ void cpa16z(uint32_t dst, const void* src, int sz) {
    asm volatile("cp.async.ca.shared.global [%0], [%1], 16, %2;" :: "r"(dst), "l"(src), "r"(sz));
}
#define CPCOMMIT() asm volatile("cp.async.commit_group;")
#define CPWAIT0()  asm volatile("cp.async.wait_group 0;")

// ---------------- warp MMA helpers (HMMA path, plain sm_103-safe) ----------
__device__ __forceinline__ void ldsm4(uint32_t* r, uint32_t addr) {
    asm volatile("ldmatrix.sync.aligned.m8n8.x4.shared.b16 {%0,%1,%2,%3}, [%4];"
        : "=r"(r[0]), "=r"(r[1]), "=r"(r[2]), "=r"(r[3]) : "r"(addr));
}
__device__ __forceinline__ void mma_bf16(float* c, const uint32_t* a, uint32_t b0, uint32_t b1) {
    asm volatile("mma.sync.aligned.m16n8k16.row.col.f32.bf16.bf16.f32 "
        "{%0,%1,%2,%3},{%4,%5,%6,%7},{%8,%9},{%0,%1,%2,%3};"
        : "+f"(c[0]), "+f"(c[1]), "+f"(c[2]), "+f"(c[3])
        : "r"(a[0]), "r"(a[1]), "r"(a[2]), "r"(a[3]), "r"(b0), "r"(b1));
}
// bf16 split helpers
__device__ __forceinline__ uint32_t cvt_bf2(float hi_elem, float lo_elem) {
    uint32_t r; asm("cvt.rn.bf16x2.f32 %0, %1, %2;" : "=r"(r) : "f"(hi_elem), "f"(lo_elem));
    return r;
}
__device__ __forceinline__ float bflo_f(uint32_t w) { return __uint_as_float(w << 16); }
__device__ __forceinline__ float bfhi_f(uint32_t w) { return __uint_as_float(w & 0xffff0000u); }

// split 16 fp32 -> bf16 hi/lo, store 2x uint4 to each of H and L at off
__device__ __forceinline__ void split16(uint8_t* Hb, uint8_t* Lb, int off,
    float4 v0, float4 v1, float4 v2, float4 v3)
{
    uint32_t h0 = cvt_bf2(v0.y, v0.x), h1 = cvt_bf2(v0.w, v0.z);
    uint32_t h2 = cvt_bf2(v1.y, v1.x), h3 = cvt_bf2(v1.w, v1.z);
    uint32_t h4 = cvt_bf2(v2.y, v2.x), h5 = cvt_bf2(v2.w, v2.z);
    uint32_t h6 = cvt_bf2(v3.y, v3.x), h7 = cvt_bf2(v3.w, v3.z);
    uint32_t l0 = cvt_bf2(v0.y - bfhi_f(h0), v0.x - bflo_f(h0));
    uint32_t l1 = cvt_bf2(v0.w - bfhi_f(h1), v0.z - bflo_f(h1));
    uint32_t l2 = cvt_bf2(v1.y - bfhi_f(h2), v1.x - bflo_f(h2));
    uint32_t l3 = cvt_bf2(v1.w - bfhi_f(h3), v1.z - bflo_f(h3));
    uint32_t l4 = cvt_bf2(v2.y - bfhi_f(h4), v2.x - bflo_f(h4));
    uint32_t l5 = cvt_bf2(v2.w - bfhi_f(h5), v2.z - bflo_f(h5));
    uint32_t l6 = cvt_bf2(v3.y - bfhi_f(h6), v3.x - bflo_f(h6));
    uint32_t l7 = cvt_bf2(v3.w - bfhi_f(h7), v3.z - bflo_f(h7));
    *(uint4*)(Hb + off)      = make_uint4(h0, h1, h2, h3);
    *(uint4*)(Hb + off + 16) = make_uint4(h4, h5, h6, h7);
    *(uint4*)(Lb + off)      = make_uint4(l0, l1, l2, l3);
    *(uint4*)(Lb + off + 16) = make_uint4(l4, l5, l6, l7);
}
// split 8 fp32 -> one uint4 each
__device__ __forceinline__ void split8(uint8_t* Hb, uint8_t* Lb, int off,
    float4 v0, float4 v1)
{
    uint32_t h0 = cvt_bf2(v0.y, v0.x), h1 = cvt_bf2(v0.w, v0.z);
    uint32_t h2 = cvt_bf2(v1.y, v1.x), h3 = cvt_bf2(v1.w, v1.z);
    uint32_t l0 = cvt_bf2(v0.y - bfhi_f(h0), v0.x - bflo_f(h0));
    uint32_t l1 = cvt_bf2(v0.w - bfhi_f(h1), v0.z - bflo_f(h1));
    uint32_t l2 = cvt_bf2(v1.y - bfhi_f(h2), v1.x - bflo_f(h2));
    uint32_t l3 = cvt_bf2(v1.w - bfhi_f(h3), v1.z - bflo_f(h3));
    *(uint4*)(Hb + off) = make_uint4(h0, h1, h2, h3);
    *(uint4*)(Lb + off) = make_uint4(l0, l1, l2, l3);
}

// ------------------------- scratch (device globals) -------------------------
__device__ __align__(16) __nv_bfloat16 g_qth[NT * D];
__device__ __align__(16) __nv_bfloat16 g_qtl[NT * D];
__device__ float g_qb[NT];
__device__ __align__(16) float g_scores[(size_t)B * NT * S];          // raw scores (kB->kC)
__device__ __align__(16) __nv_bfloat16 g_ath[(size_t)B * NT * S];     // attn hi (kC->kD)
__device__ __align__(16) __nv_bfloat16 g_atl[(size_t)B * NT * S];     // attn lo
__device__ __align__(16) float g_pooled[(size_t)B * NT * D];
__device__ __align__(16) float g_ctx[NTOK * D];
__device__ __align__(16) float g_ao[NTOK * D];
__device__ __align__(16) __nv_bfloat16 g_xlh[NTOK * D];
__device__ __align__(16) __nv_bfloat16 g_xll[NTOK * D];
__device__ __align__(16) __nv_bfloat16 g_hh[(size_t)NPAIR * H];
__device__ __align__(16) __nv_bfloat16 g_hl[(size_t)NPAIR * H];
__device__ float g_probs[NTOK * E];
__device__ int   g_topi[NTOK * TOPK];
__device__ float g_topw[NTOK * TOPK];
__device__ int   g_ecnt[E];
__device__ int   g_elist[E * NPAIR];
__device__ __align__(16) float g_y[(size_t)NPAIR * D];

__device__ __forceinline__ float wred(float v) {
#pragma unroll
    for (int o = 16; o > 0; o >>= 1) v += __shfl_down_sync(0xffffffffu, v, o);
    return v;
}
__device__ __forceinline__ float wredmax(float v) {
#pragma unroll
    for (int o = 16; o > 0; o >>= 1) v = fmaxf(v, __shfl_down_sync(0xffffffffu, v, o));
    return v;
}
__device__ __forceinline__ int wredi(int v) {
#pragma unroll
    for (int o = 16; o > 0; o >>= 1) v += __shfl_down_sync(0xffffffffu, v, o);
    return v;
}
__device__ __forceinline__ float gelu_tanh(float x) {
    return 0.5f * x * (1.f + tanhf(0.7978845608028654f * (x + 0.044715f * x * x * x)));
}

// ------------------------- kA: qtilde = (probe@Wq^T + bq) @ Wk --------------
__global__ __launch_bounds__(256) void kA_qtilde(
    const float* __restrict__ probe, const float* __restrict__ ipw,
    const float* __restrict__ ipb)
{
    int ht = blockIdx.x;
    int h = ht >> 2, t = ht & 3;
    __shared__ float q_s[HD];
    int tid = threadIdx.x, lane = tid & 31, warp = tid >> 5;

    for (int j = warp; j < HD; j += 8) {
        int row = h * HD + j;
        const float* w = ipw + (size_t)row * D;
        const float* p = probe + t * D;
        float acc = 0.f;
        for (int dd = lane; dd < D; dd += 32) acc += p[dd] * w[dd];
        acc = wred(acc);
        if (lane == 0) q_s[j] = acc + ipb[row];
    }
    __syncthreads();
    if (tid == 0) {
        float qb = 0.f;
        for (int j = 0; j < HD; j++) qb += q_s[j] * ipb[D + h * HD + j];
        g_qb[ht] = qb;
    }
    for (int dd = tid; dd < D; dd += 256) {
        float acc = 0.f;
        const float* wk = ipw + (size_t)(D + h * HD) * D + dd;
#pragma unroll 8
        for (int j = 0; j < HD; j++) acc += q_s[j] * wk[(size_t)j * D];
        __nv_bfloat16 hb = __float2bfloat16(acc);
        float hf = __bfloat162float(hb);
        g_qth[ht * D + dd] = hb;
        g_qtl[ht * D + dd] = __float2bfloat16(acc - hf);
    }
}

// ------------------------- kB: scores, double-buffered, k-split warps -------
// (R14 configuration: launch_bounds(256,2), k-split across warp halves)
#define KB_SMEM 56512
__global__ __launch_bounds__(256, 2) void kB_scores_mma(const float* __restrict__ hidden)
{
    extern __shared__ __align__(16) uint8_t dsm[];
    uint8_t* AH = dsm;
    uint8_t* AL = dsm + 20480;
    float* qbs = (float*)(dsm + 56320);
    uint32_t base = sptr(dsm);
    uint32_t ah_s = base, bh_s = base + 40960, bl_s = base + 48640;

    int b = blockIdx.y;
    int s0 = blockIdx.x * 128;
    int tid = threadIdx.x, lane = tid & 31, wid = tid >> 5;
    int wq = wid & 3, ksw = wid >> 2;
    uint32_t kso = (uint32_t)(ksw * 32);

    if (tid < NT) qbs[tid] = g_qb[tid];

    int arow = tid & 127, ahalf = tid >> 7;
    const float* hrow = hidden + ((size_t)b * S + s0 + arow) * D + ahalf * 16;
    int aoff = arow * 80 + ahalf * 32;
    int brow = tid >> 2, bu = tid & 3;
    uint32_t boff = (uint32_t)(brow * 80 + bu * 16);

    float4 pv0 = *(const float4*)(hrow + 0);
    float4 pv1 = *(const float4*)(hrow + 4);
    float4 pv2 = *(const float4*)(hrow + 8);
    float4 pv3 = *(const float4*)(hrow + 12);

    float acc[2][6][4];
#pragma unroll
    for (int s = 0; s < 2; s++)
#pragma unroll
        for (int i = 0; i < 6; i++) { acc[s][i][0] = acc[s][i][1] = acc[s][i][2] = acc[s][i][3] = 0.f; }

    uint32_t a_addr = ah_s + (uint32_t)((wq * 32 + (lane & 15)) * 80 + (lane >> 4) * 16);
    int bmi = lane >> 3;
    uint32_t b_off = (uint32_t)(((bmi >> 1) * 8 + (lane & 7)) * 80 + (bmi & 1) * 16);

    // prologue
    if (tid < 192) {
        cpa16(bh_s + boff, g_qth + (size_t)brow * D + bu * 8);
        cpa16(bl_s + boff, g_qtl + (size_t)brow * D + bu * 8);
    }
    CPCOMMIT();
    split16(AH, AL, aoff, pv0, pv1, pv2, pv3);
    {
        const float* nx = hrow + 32;
        pv0 = *(const float4*)(nx + 0); pv1 = *(const float4*)(nx + 4);
        pv2 = *(const float4*)(nx + 8); pv3 = *(const float4*)(nx + 12);
    }
    CPWAIT0();
    __syncthreads();

    const int NCH = D / 32;   // 24
    for (int ch = 0; ch < NCH; ch++) {
        int cur = ch & 1, nxt = cur ^ 1;
        if (ch + 1 < NCH) {
            int k1 = (ch + 1) * 32;
            if (tid < 192) {
                cpa16(bh_s + (uint32_t)(nxt * 3840) + boff, g_qth + (size_t)brow * D + k1 + bu * 8);
                cpa16(bl_s + (uint32_t)(nxt * 3840) + boff, g_qtl + (size_t)brow * D + k1 + bu * 8);
            }
            CPCOMMIT();
        }
        {
            uint32_t bhf[12], blf[12];
#pragma unroll
            for (int j = 0; j < 3; j++) {
                uint32_t badd = (uint32_t)(cur * 3840 + j * 16 * 80) + b_off + kso;
                ldsm4(bhf + 4 * j, bh_s + badd);
                ldsm4(blf + 4 * j, bl_s + badd);
            }
#pragma unroll
            for (int s = 0; s < 2; s++) {
                uint32_t ahf[4], alf[4];
                uint32_t aadd = a_addr + (uint32_t)(cur * 10240 + s * 1280) + kso;
                ldsm4(ahf, aadd);
                ldsm4(alf, aadd + 20480u);
#pragma unroll
                for (int j = 0; j < 3; j++) {
                    mma_bf16(acc[s][2 * j], ahf, bhf[4 * j], bhf[4 * j + 1]);
                    mma_bf16(acc[s][2 * j], ahf, blf[4 * j], blf[4 * j + 1]);
                    mma_bf16(acc[s][2 * j], alf, bhf[4 * j], bhf[4 * j + 1]);
                    mma_bf16(acc[s][2 * j + 1], ahf, bhf[4 * j + 2], bhf[4 * j + 3]);
                    mma_bf16(acc[s][2 * j + 1], ahf, blf[4 * j + 2], blf[4 * j + 3]);
                    mma_bf16(acc[s][2 * j + 1], alf, bhf[4 * j + 2], bhf[4 * j + 3]);
                }
            }
        }
        if (ch + 1 < NCH) {
            split16(AH + nxt * 10240, AL + nxt * 10240, aoff, pv0, pv1, pv2, pv3);
            if (ch + 2 < NCH) {
                const float* nx = hrow + (ch + 2) * 32;
                pv0 = *(const float4*)(nx + 0); pv1 = *(const float4*)(nx + 4);
                pv2 = *(const float4*)(nx + 8); pv3 = *(const float4*)(nx + 12);
            }
            CPWAIT0();
        }
        __syncthreads();
    }
    // k-parity reduction: warps 4-7 dump accs, warps 0-3 combine + store
    float* red = (float*)dsm;
    if (ksw == 1) {
        float* dst = red + (size_t)(wq * 32 + lane) * 48;
#pragma unroll
        for (int s = 0; s < 2; s++)
#pragma unroll
            for (int i = 0; i < 6; i++)
#pragma unroll
                for (int f = 0; f < 4; f++) dst[(s * 6 + i) * 4 + f] = acc[s][i][f];
    }
    __syncthreads();
    if (ksw == 0) {
        const float* src = red + (size_t)(wq * 32 + lane) * 48;
        int g = lane >> 2, t4 = lane & 3;
        float* outb = g_scores + (size_t)b * NT * S;
#pragma unroll
        for (int s = 0; s < 2; s++) {
            int srow = s0 + (wq * 2 + s) * 16 + g;
#pragma unroll
            for (int nf = 0; nf < 6; nf++) {
                int n0 = nf * 8 + t4 * 2;
                float c0 = acc[s][nf][0] + src[(s * 6 + nf) * 4 + 0];
                float c1 = acc[s][nf][1] + src[(s * 6 + nf) * 4 + 1];
                float c2 = acc[s][nf][2] + src[(s * 6 + nf) * 4 + 2];
                float c3 = acc[s][nf][3] + src[(s * 6 + nf) * 4 + 3];
                outb[(size_t)n0 * S + srow]           = 0.125f * (c0 + qbs[n0]);
                outb[(size_t)(n0 + 1) * S + srow]     = 0.125f * (c1 + qbs[n0 + 1]);
                outb[(size_t)n0 * S + srow + 8]       = 0.125f * (c2 + qbs[n0]);
                outb[(size_t)(n0 + 1) * S + srow + 8] = 0.125f * (c3 + qbs[n0 + 1]);
            }
        }
    }
}

// ------------------------- kC: softmax + head-mean; write attn bf16 hi/lo ---
__global__ __launch_bounds__(384) void kC_softmax(float* __restrict__ out_aw)
{
    int bt = blockIdx.x, b = bt >> 2, t = bt & 3;
    __shared__ float stage[NH][S];
    int tid = threadIdx.x, lane = tid & 31, warp = tid >> 5;

    size_t rowoff = ((size_t)b * NT + warp * T + t) * S;
    const float* row = g_scores + rowoff;
    float4 v[8];
#pragma unroll
    for (int i = 0; i < 8; i++) v[i] = *(const float4*)(row + i * 128 + lane * 4);
    float m = -1e30f;
#pragma unroll
    for (int i = 0; i < 8; i++)
        m = fmaxf(m, fmaxf(fmaxf(v[i].x, v[i].y), fmaxf(v[i].z, v[i].w)));
    m = wredmax(m);
    m = __shfl_sync(0xffffffffu, m, 0);
    float sum = 0.f;
#pragma unroll
    for (int i = 0; i < 8; i++) {
        v[i].x = __expf(v[i].x - m); v[i].y = __expf(v[i].y - m);
        v[i].z = __expf(v[i].z - m); v[i].w = __expf(v[i].w - m);
        sum += v[i].x + v[i].y + v[i].z + v[i].w;
    }
    sum = wred(sum);
    float inv = 1.f / __shfl_sync(0xffffffffu, sum, 0);
#pragma unroll
    for (int i = 0; i < 8; i++) {
        v[i].x *= inv; v[i].y *= inv; v[i].z *= inv; v[i].w *= inv;
        *(float4*)&stage[warp][i * 128 + lane * 4] = v[i];
        uint32_t h0 = cvt_bf2(v[i].y, v[i].x), h1 = cvt_bf2(v[i].w, v[i].z);
        uint32_t l0 = cvt_bf2(v[i].y - bfhi_f(h0), v[i].x - bflo_f(h0));
        uint32_t l1 = cvt_bf2(v[i].w - bfhi_f(h1), v[i].z - bflo_f(h1));
        size_t idx = rowoff + i * 128 + lane * 4;
        *(uint2*)&g_ath[idx] = make_uint2(h0, h1);
        *(uint2*)&g_atl[idx] = make_uint2(l0, l1);
    }
    __syncthreads();
    const float inv12 = 1.f / 12.f;
#pragma unroll
    for (int r = 0; r < 3; r++) {
        int s = tid + 384 * r;
        if (s < S) {
            float a = 0.f;
#pragma unroll
            for (int h = 0; h < NH; h++) a += stage[h][s];
            out_aw[(size_t)bt * S + s] = a * inv12;
        }
    }
}

// ------------------------- kD: pooled, cp.async A, 3 CTAs/SM ----------------
#define KD_SMEM 56320
__global__ __launch_bounds__(256, 3) void kD_pooled_mma(const float* __restrict__ hidden)
{
    extern __shared__ __align__(16) uint8_t dsm[];
    uint8_t* BH = dsm + 15360;
    uint8_t* BL = dsm + 35840;
    uint32_t base = sptr(dsm);
    uint32_t ah_s = base, al_s = base + 7680, bh_s = base + 15360, bl_s = base + 35840;

    int b = blockIdx.y;
    int n0 = blockIdx.x * 128;
    int tid = threadIdx.x, lane = tid & 31, wid = tid >> 5;

    int am = tid >> 2, au = tid & 3;
    size_t arowo = ((size_t)b * NT + (am < NT ? am : 0)) * S + au * 8;
    uint32_t a_stoff = (uint32_t)(am * 80 + au * 16);

    int bn = tid & 127, bkg = tid >> 7;
    const float* hcol = hidden + ((size_t)b * S + bkg * 16) * D + n0 + bn;
    int b_st = bn * 80 + bkg * 32;

    float hb0[8];
#pragma unroll
    for (int j = 0; j < 8; j++) hb0[j] = hcol[(size_t)j * D];

    float acc[3][2][4];
#pragma unroll
    for (int i = 0; i < 3; i++)
#pragma unroll
        for (int f = 0; f < 2; f++) { acc[i][f][0] = acc[i][f][1] = acc[i][f][2] = acc[i][f][3] = 0.f; }

    uint32_t aA[3];
#pragma unroll
    for (int st = 0; st < 3; st++)
        aA[st] = ah_s + (uint32_t)((st * 16 + (lane & 15)) * 80 + (lane >> 4) * 16);
    int bmi = lane >> 3;
    uint32_t b_off = (uint32_t)((wid * 16 + (bmi >> 1) * 8 + (lane & 7)) * 80 + (bmi & 1) * 16);

    if (tid < 192) {
        cpa16(ah_s + a_stoff, g_ath + arowo);
        cpa16(al_s + a_stoff, g_atl + arowo);
    }
    CPCOMMIT();
    split8(dsm + 15360, dsm + 35840, b_st,
           make_float4(hb0[0], hb0[1], hb0[2], hb0[3]),
           make_float4(hb0[4], hb0[5], hb0[6], hb0[7]));
    {
        float4 q0 = make_float4(hcol[8 * (size_t)D], hcol[9 * (size_t)D], hcol[10 * (size_t)D], hcol[11 * (size_t)D]);
        float4 q1 = make_float4(hcol[12 * (size_t)D], hcol[13 * (size_t)D], hcol[14 * (size_t)D], hcol[15 * (size_t)D]);
        split8(BH, BL, b_st + 16, q0, q1);
    }
#pragma unroll
    for (int j = 0; j < 8; j++) hb0[j] = hcol[(size_t)(32 + j) * D];
    CPWAIT0();
    __syncthreads();

    const int NCH = S / 32;   // 32
    for (int ch = 0; ch < NCH; ch++) {
        int cur = ch & 1, nxt = cur ^ 1;
        if (ch + 1 < NCH) {
            int k1 = (ch + 1) * 32;
            if (tid < 192) {
                cpa16(ah_s + (uint32_t)(nxt * 3840) + a_stoff, g_ath + arowo + k1);
                cpa16(al_s + (uint32_t)(nxt * 3840) + a_stoff, g_atl + arowo + k1);
            }
            CPCOMMIT();
        }
#pragma unroll
        for (int ks = 0; ks < 2; ks++) {
            uint32_t bhf[4], blf[4];
            ldsm4(bhf, bh_s + (uint32_t)(cur * 10240) + b_off + ks * 32);
            ldsm4(blf, bl_s + (uint32_t)(cur * 10240) + b_off + ks * 32);
#pragma unroll
            for (int st = 0; st < 3; st++) {
                uint32_t ahf[4], alf[4];
                uint32_t aadd = aA[st] + (uint32_t)(cur * 3840) + ks * 32;
                ldsm4(ahf, aadd);
                ldsm4(alf, aadd + 7680u);
                mma_bf16(acc[st][0], ahf, bhf[0], bhf[1]);
                mma_bf16(acc[st][0], ahf, blf[0], blf[1]);
                mma_bf16(acc[st][0], alf, bhf[0], bhf[1]);
                mma_bf16(acc[st][1], ahf, bhf[2], bhf[3]);
                mma_bf16(acc[st][1], ahf, blf[2], blf[3]);
                mma_bf16(acc[st][1], alf, bhf[2], bhf[3]);
            }
        }
        if (ch + 1 < NCH) {
            int k1 = (ch + 1) * 32;
            split8(BH + nxt * 10240, BL + nxt * 10240, b_st,
                   make_float4(hb0[0], hb0[1], hb0[2], hb0[3]),
                   make_float4(hb0[4], hb0[5], hb0[6], hb0[7]));
            {
                const float* hc = hcol + (size_t)k1 * D;
                float4 q0 = make_float4(hc[8 * (size_t)D], hc[9 * (size_t)D], hc[10 * (size_t)D], hc[11 * (size_t)D]);
                float4 q1 = make_float4(hc[12 * (size_t)D], hc[13 * (size_t)D], hc[14 * (size_t)D], hc[15 * (size_t)D]);
                split8(BH + nxt * 10240, BL + nxt * 10240, b_st + 16, q0, q1);
            }
            if (ch + 2 < NCH) {
                int k2 = (ch + 2) * 32;
                const float* hc2 = hcol + (size_t)k2 * D;
#pragma unroll
                for (int j = 0; j < 8; j++) hb0[j] = hc2[(size_t)j * D];
            }
            CPWAIT0();
        }
        __syncthreads();
    }
    int g = lane >> 2, t4 = lane & 3;
#pragma unroll
    for (int st = 0; st < 3; st++) {
        int m = st * 16 + g;
        float* base0 = g_pooled + ((size_t)b * NT + m) * D + n0;
        float* base1 = g_pooled + ((size_t)b * NT + m + 8) * D + n0;
#pragma unroll
        for (int f = 0; f < 2; f++) {
            int n = wid * 16 + f * 8 + t4 * 2;
            base0[n]     = acc[st][f][0];
            base0[n + 1] = acc[st][f][1];
            base1[n]     = acc[st][f][2];
            base1[n + 1] = acc[st][f][3];
        }
    }
}

// ------------------------- kE1: v-proj via mma.sync bf16-split --------------
__global__ __launch_bounds__(256, 2) void kE1_vproj_mma(
    const float* __restrict__ ipw, const float* __restrict__ ipb)
{
    __shared__ __align__(16) uint8_t AH[64 * 80];
    __shared__ __align__(16) uint8_t AL[64 * 80];
    __shared__ __align__(16) uint8_t BH[64 * 80];
    __shared__ __align__(16) uint8_t BL[64 * 80];

    int h = blockIdx.x;
    int tok0 = blockIdx.y * 64;
    int tid = threadIdx.x, lane = tid & 31, wid = tid >> 5;
    int st = wid & 3, nh = wid >> 2;

    uint32_t ah_s = sptr(AH), al_s = sptr(AL), bh_s = sptr(BH), bl_s = sptr(BL);

    int arow = tid >> 2, aq = tid & 3;
    const float* wrow = ipw + (size_t)(2 * D + h * HD + arow) * D + aq * 8;
    int tk = tok0 + (tid >> 2);
    const float* prow = g_pooled + ((size_t)(tk >> 2) * NT + h * T + (tk & 3)) * D + aq * 8;

    float4 pa0 = *(const float4*)wrow, pa1 = *(const float4*)(wrow + 4);
    float4 pb0 = *(const float4*)prow, pb1 = *(const float4*)(prow + 4);

    float acc[4][4];
#pragma unroll
    for (int i = 0; i < 4; i++) { acc[i][0] = acc[i][1] = acc[i][2] = acc[i][3] = 0.f; }

    uint32_t a_addr = ah_s + (uint32_t)((st * 16 + (lane & 15)) * 80 + (lane >> 4) * 16);
    uint32_t al_addr = a_addr + (al_s - ah_s);
    int bmi = lane >> 3;
    uint32_t b_off = (uint32_t)((nh * 32 + (bmi >> 1) * 8 + (lane & 7)) * 80 + (bmi & 1) * 16);

    const int NCH = D / 32;
    for (int ch = 0; ch < NCH; ch++) {
        {
            int off = arow * 80 + aq * 16;
            split8(AH, AL, off, pa0, pa1);
            split8(BH, BL, off, pb0, pb1);
        }
        __syncthreads();
        if (ch + 1 < NCH) {
            int k1 = (ch + 1) * 32;
            pa0 = *(const float4*)(wrow + k1);
            pa1 = *(const float4*)(wrow + k1 + 4);
            pb0 = *(const float4*)(prow + k1);
            pb1 = *(const float4*)(prow + k1 + 4);
        }
#pragma unroll
        for (int ks = 0; ks < 2; ks++) {
            uint32_t ahf[4], alf[4];
            ldsm4(ahf, a_addr + ks * 32);
            ldsm4(alf, al_addr + ks * 32);
#pragma unroll
            for (int j = 0; j < 2; j++) {
                uint32_t bhf[4], blf[4];
                uint32_t badd = (uint32_t)(j * 16 * 80 + ks * 32) + b_off;
                ldsm4(bhf, bh_s + badd);
                ldsm4(blf, bl_s + badd);
                mma_bf16(acc[2 * j], ahf, bhf[0], bhf[1]);
                mma_bf16(acc[2 * j], ahf, blf[0], blf[1]);
                mma_bf16(acc[2 * j], alf, bhf[0], bhf[1]);
                mma_bf16(acc[2 * j + 1], ahf, bhf[2], bhf[3]);
                mma_bf16(acc[2 * j + 1], ahf, blf[2], blf[3]);
                mma_bf16(acc[2 * j + 1], alf, bhf[2], bhf[3]);
            }
        }
        __syncthreads();
    }
    int g = lane >> 2, t4 = lane & 3;
    int jA = h * HD + st * 16 + g;
    int jB = jA + 8;
    float bA = ipb[2 * D + jA], bB = ipb[2 * D + jB];
#pragma unroll
    for (int nf = 0; nf < 4; nf++) {
        int tkc = tok0 + nh * 32 + nf * 8 + t4 * 2;
        g_ctx[(size_t)tkc * D + jA]       = acc[nf][0] + bA;
        g_ctx[(size_t)(tkc + 1) * D + jA] = acc[nf][1] + bA;
        g_ctx[(size_t)tkc * D + jB]       = acc[nf][2] + bB;
        g_ctx[(size_t)(tkc + 1) * D + jB] = acc[nf][3] + bB;
    }
}

// ------------------------- kE2: out-proj GEMM + residual --------------------
__global__ __launch_bounds__(256) void kE2_outproj(
    const float* __restrict__ opw, const float* __restrict__ opb,
    float* __restrict__ out_y)
{
    int r0 = blockIdx.x * 128;
    int t0 = blockIdx.y * 32;
    __shared__ __align__(16) float cs[32 * 17];
    __shared__ __align__(16) float ws[16 * 132 + 16];
    int tid = threadIdx.x;
    int tr = tid & 31;
    int tt = tid >> 5;
    f32x2 acc[4][2];
#pragma unroll
    for (int t = 0; t < 4; t++) { acc[t][0] = 0ull; acc[t][1] = 0ull; }

    for (int k0 = 0; k0 < D; k0 += 16) {
#pragma unroll
        for (int r = 0; r < 2; r++) {
            int idx = tid + 256 * r;
            int tok = idx >> 4, kk = idx & 15;
            cs[tok * 17 + kk] = g_ctx[(size_t)(t0 + tok) * D + k0 + kk];
        }
#pragma unroll
        for (int r = 0; r < 2; r++) {
            int idx = tid + 256 * r;
            int rr = idx >> 2, ko = (idx & 3) << 2;
            float4 v = *(const float4*)(opw + (size_t)(r0 + rr) * D + k0 + ko);
            float* base = &ws[ko * 132 + rr + ko];
            base[0] = v.x; base[132] = v.y; base[264] = v.z; base[396] = v.w;
        }
        __syncthreads();
#pragma unroll 4
        for (int kk = 0; kk < 16; kk++) {
            ulonglong2 wu = *(const ulonglong2*)(&ws[kk * 132 + (kk & 12)] + tr * 4);
#pragma unroll
            for (int t = 0; t < 4; t++) {
                f32x2 ad = dup2(cs[(tt * 4 + t) * 17 + kk]);
                fma2(acc[t][0], wu.x, ad);
                fma2(acc[t][1], wu.y, ad);
            }
        }
        __syncthreads();
    }
    float4 bb = *(const float4*)&opb[r0 + tr * 4];
#pragma unroll
    for (int t = 0; t < 4; t++) {
        int tok = t0 + tt * 4 + t;
        float2 u0 = unpk(acc[t][0]), u1 = unpk(acc[t][1]);
        float4 o = make_float4(u0.x + bb.x, u0.y + bb.y, u1.x + bb.z, u1.y + bb.w);
        *(float4*)&out_y[(size_t)tok * D + r0 + tr * 4] = o;
        *(float4*)&g_ao[(size_t)tok * D + r0 + tr * 4] = o;
    }
}

// ------------------------- kE3: LN + gate + top2, per token -----------------
__global__ __launch_bounds__(256) void kE3_ln_gate(
    const float* __restrict__ lnw, const float* __restrict__ lnb,
    const float* __restrict__ gw)
{
    int tok = blockIdx.x;
    int t = tok & 3;
    __shared__ float x[D];
    __shared__ float red[256];
    __shared__ float lg[E];
    int tid = threadIdx.x, lane = tid & 31, warp = tid >> 5;

    float v0 = g_ao[(size_t)tok * D + tid];
    float v1 = g_ao[(size_t)tok * D + tid + 256];
    float v2 = g_ao[(size_t)tok * D + tid + 512];
    red[tid] = v0 + v1 + v2; __syncthreads();
    for (int o = 128; o > 0; o >>= 1) { if (tid < o) red[tid] += red[tid + o]; __syncthreads(); }
    float mu = red[0] * (1.f / 768.f); __syncthreads();
    float d0 = v0 - mu, d1 = v1 - mu, d2 = v2 - mu;
    red[tid] = d0 * d0 + d1 * d1 + d2 * d2; __syncthreads();
    for (int o = 128; o > 0; o >>= 1) { if (tid < o) red[tid] += red[tid + o]; __syncthreads(); }
    float rstd = rsqrtf(red[0] * (1.f / 768.f) + 1e-6f); __syncthreads();

#pragma unroll
    for (int r = 0; r < 3; r++) {
        int dd = tid + 256 * r;
        float dv = (r == 0) ? d0 : (r == 1) ? d1 : d2;
        float xv = dv * rstd * lnw[dd] + lnb[dd];
        x[dd] = xv;
        __nv_bfloat16 hb = __float2bfloat16(xv);
        g_xlh[(size_t)tok * D + dd] = hb;
        g_xll[(size_t)tok * D + dd] = __float2bfloat16(xv - __bfloat162float(hb));
    }
    __syncthreads();

    if (warp < E) {
        float acc = 0.f;
        for (int dd = lane; dd < D; dd += 32)
            acc += x[dd] * gw[((size_t)t * D + dd) * E + warp];
        acc = wred(acc);
        if (lane == 0) lg[warp] = acc;
    }
    __syncthreads();
    if (tid == 0) {
        float p[E];
        float mx = lg[0];
        for (int e = 1; e < E; e++) mx = fmaxf(mx, lg[e]);
        float sum = 0.f;
        for (int e = 0; e < E; e++) { p[e] = __expf(lg[e] - mx); sum += p[e]; }
        float inv = 1.f / sum;
        for (int e = 0; e < E; e++) { p[e] *= inv; g_probs[tok * E + e] = p[e]; }
        int i0 = 0;
        for (int e = 1; e < E; e++) if (p[e] > p[i0]) i0 = e;
        int i1 = (i0 == 0) ? 1 : 0;
        for (int e = 0; e < E; e++) if (e != i0 && p[e] > p[i1]) i1 = e;
        float inv2 = 1.f / (p[i0] + p[i1]);
        g_topi[tok * 2] = i0; g_topi[tok * 2 + 1] = i1;
        g_topw[tok * 2] = p[i0] * inv2; g_topw[tok * 2 + 1] = p[i1] * inv2;
    }
}

// ------------------------- kF: routing lists + moe_loss ---------------------
__global__ __launch_bounds__(256) void kF_route(float* __restrict__ out_loss)
{
    __shared__ int ti[NPAIR];
    __shared__ float imp_s[E];
    __shared__ int disp_s[E];
    int tid = threadIdx.x, lane = tid & 31, warp = tid >> 5;
    for (int i = tid; i < NPAIR; i += 256) ti[i] = g_topi[i];
    __syncthreads();
    if (warp < E) {
        float acc = 0.f;
        for (int tok = lane; tok < NTOK; tok += 32) acc += g_probs[tok * E + warp];
        int cnt = 0;
        for (int p = lane; p < NPAIR; p += 32) cnt += (ti[p] == warp);
        acc = wred(acc); cnt = wredi(cnt);
        if (lane == 0) { imp_s[warp] = acc * (1.f / NTOK); disp_s[warp] = cnt; }
    }
    __syncthreads();
    if (tid == 0) {
        float loss = 0.f;
        for (int e = 0; e < E; e++) loss += imp_s[e] * ((float)disp_s[e] * (1.f / NTOK));
        out_loss[0] = (float)E * loss;
    }
    if (tid < E) {
        int c = 0;
        for (int p = 0; p < NPAIR; p++)
            if (ti[p] == tid) g_elist[tid * NPAIR + (c++)] = p;
        g_ecnt[tid] = c;
    }
}

// ------------------------- kG/kH: MoE GEMMs, double-buffered -----------------
#define GM_SMEM 61696
#define GM_CH 64
__global__ __launch_bounds__(256, 2) void kG_fc1_mma(
    const float* __restrict__ w1, const float* __restrict__ b1)
{
    extern __shared__ __align__(16) uint8_t dsm[];
    uint8_t* AH = dsm;
    uint8_t* AL = dsm + 20480;
    int* plist = (int*)(dsm + 61440);
    uint32_t base = sptr(dsm);
    uint32_t ah_s = base, bh_s = base + 40960, bl_s = base + 51200;

    int h0 = blockIdx.x * 128;
    int e = blockIdx.y;
    int c0 = blockIdx.z * GM_CH;
    int nt = g_ecnt[e];
    if (c0 >= nt) return;
    int ctn = min(GM_CH, nt - c0);
    int tid = threadIdx.x, lane = tid & 31, wid = tid >> 5;
    if (tid < GM_CH) plist[tid] = (tid < ctn) ? g_elist[e * NPAIR + c0 + tid] : -1;
    __syncthreads();

    int arow = tid & 127, ahalf = tid >> 7;
    const float* wrow = w1 + ((size_t)e * H + h0 + arow) * D + ahalf * 16;
    int aoff = arow * 80 + ahalf * 32;

    int brow = tid >> 2, bu = tid & 3;
    uint32_t boff = (uint32_t)(brow * 80 + bu * 16);
    int bp = plist[brow];
    int bok = (bp >= 0) ? 16 : 0;
    const __nv_bfloat16* xh = g_xlh + ((bp >= 0) ? (size_t)(bp >> 1) * D : 0) + bu * 8;
    const __nv_bfloat16* xl = g_xll + ((bp >= 0) ? (size_t)(bp >> 1) * D : 0) + bu * 8;

    float4 pv0 = *(const float4*)(wrow + 0);
    float4 pv1 = *(const float4*)(wrow + 4);
    float4 pv2 = *(const float4*)(wrow + 8);
    float4 pv3 = *(const float4*)(wrow + 12);

    float acc[8][4];
#pragma unroll
    for (int i = 0; i < 8; i++) { acc[i][0] = acc[i][1] = acc[i][2] = acc[i][3] = 0.f; }

    uint32_t a_addr = ah_s + (uint32_t)((wid * 16 + (lane & 15)) * 80 + (lane >> 4) * 16);
    int bmi = lane >> 3;
    uint32_t b_off = (uint32_t)(((bmi >> 1) * 8 + (lane & 7)) * 80 + (bmi & 1) * 16);

    cpa16z(bh_s + boff, xh, bok);
    cpa16z(bl_s + boff, xl, bok);
    CPCOMMIT();
    split16(AH, AL, aoff, pv0, pv1, pv2, pv3);
    {
        const float* nx = wrow + 32;
        pv0 = *(const float4*)(nx + 0); pv1 = *(const float4*)(nx + 4);
        pv2 = *(const float4*)(nx + 8); pv3 = *(const float4*)(nx + 12);
    }
    CPWAIT0();
    __syncthreads();

    const int NCH = D / 32;   // 24
    for (int ch = 0; ch < NCH; ch++) {
        int cur = ch & 1, nxt = cur ^ 1;
        if (ch + 1 < NCH) {
            int k1 = (ch + 1) * 32;
            cpa16z(bh_s + (uint32_t)(nxt * 5120) + boff, xh + k1, bok);
            cpa16z(bl_s + (uint32_t)(nxt * 5120) + boff, xl + k1, bok);
            CPCOMMIT();
        }
#pragma unroll
        for (int ks = 0; ks < 2; ks++) {
            uint32_t ahf[4], alf[4];
            ldsm4(ahf, a_addr + (uint32_t)(cur * 10240) + ks * 32);
            ldsm4(alf, a_addr + 20480u + (uint32_t)(cur * 10240) + ks * 32);
#pragma unroll
            for (int j = 0; j < 4; j++) {
                uint32_t bhf[4], blf[4];
                uint32_t badd = (uint32_t)(cur * 5120 + j * 16 * 80 + ks * 32) + b_off;
                ldsm4(bhf, bh_s + badd);
                ldsm4(blf, bl_s + badd);
                mma_bf16(acc[2 * j], ahf, bhf[0], bhf[1]);
                mma_bf16(acc[2 * j], ahf, blf[0], blf[1]);
                mma_bf16(acc[2 * j], alf, bhf[0], bhf[1]);
                mma_bf16(acc[2 * j + 1], ahf, bhf[2], bhf[3]);
                mma_bf16(acc[2 * j + 1], ahf, blf[2], blf[3]);
                mma_bf16(acc[2 * j + 1], alf, bhf[2], bhf[3]);
            }
        }
        if (ch + 1 < NCH) {
            split16(AH + nxt * 10240, AL + nxt * 10240, aoff, pv0, pv1, pv2, pv3);
            if (ch + 2 < NCH) {
                const float* nx = wrow + (ch + 2) * 32;
                pv0 = *(const float4*)(nx + 0); pv1 = *(const float4*)(nx + 4);
                pv2 = *(const float4*)(nx + 8); pv3 = *(const float4*)(nx + 12);
            }
            CPWAIT0();
        }
        __syncthreads();
    }
    int g = lane >> 2, t4 = lane & 3;
    int hhA = h0 + wid * 16 + g;
    int hhB = hhA + 8;
    float bA = b1[e * H + hhA], bB = b1[e * H + hhB];
#pragma unroll
    for (int nf = 0; nf < 8; nf++) {
        int tok = nf * 8 + t4 * 2;
        if (tok < ctn) {
            int p = plist[tok];
            float vA = gelu_tanh(acc[nf][0] + bA);
            float vB = gelu_tanh(acc[nf][2] + bB);
            __nv_bfloat16 ha = __float2bfloat16(vA);
            __nv_bfloat16 hb2 = __float2bfloat16(vB);
            g_hh[(size_t)p * H + hhA] = ha;
            g_hl[(size_t)p * H + hhA] = __float2bfloat16(vA - __bfloat162float(ha));
            g_hh[(size_t)p * H + hhB] = hb2;
            g_hl[(size_t)p * H + hhB] = __float2bfloat16(vB - __bfloat162float(hb2));
        }
        if (tok + 1 < ctn) {
            int p = plist[tok + 1];
            float vA = gelu_tanh(acc[nf][1] + bA);
            float vB = gelu_tanh(acc[nf][3] + bB);
            __nv_bfloat16 ha = __float2bfloat16(vA);
            __nv_bfloat16 hb2 = __float2bfloat16(vB);
            g_hh[(size_t)p * H + hhA] = ha;
            g_hl[(size_t)p * H + hhA] = __float2bfloat16(vA - __bfloat162float(ha));
            g_hh[(size_t)p * H + hhB] = hb2;
            g_hl[(size_t)p * H + hhB] = __float2bfloat16(vB - __bfloat162float(hb2));
        }
    }
}

__global__ __launch_bounds__(256, 2) void kH_fc2_mma(
    const float* __restrict__ w2, const float* __restrict__ b2)
{
    extern __shared__ __align__(16) uint8_t dsm[];
    uint8_t* AH = dsm;
    uint8_t* AL = dsm + 20480;
    int* plist = (int*)(dsm + 61440);
    uint32_t base = sptr(dsm);
    uint32_t ah_s = base, bh_s = base + 40960, bl_s = base + 51200;

    int n0 = blockIdx.x * 128;
    int e = blockIdx.y;
    int c0 = blockIdx.z * GM_CH;
    int nt = g_ecnt[e];
    if (c0 >= nt) return;
    int ctn = min(GM_CH, nt - c0);
    int tid = threadIdx.x, lane = tid & 31, wid = tid >> 5;
    if (tid < GM_CH) plist[tid] = (tid < ctn) ? g_elist[e * NPAIR + c0 + tid] : -1;
    __syncthreads();

    int arow = tid & 127, ahalf = tid >> 7;
    const float* wrow = w2 + ((size_t)e * D + n0 + arow) * H + ahalf * 16;
    int aoff = arow * 80 + ahalf * 32;

    int brow = tid >> 2, bu = tid & 3;
    uint32_t boff = (uint32_t)(brow * 80 + bu * 16);
    int bp = plist[brow];
    int bok = (bp >= 0) ? 16 : 0;
    const __nv_bfloat16* xh = g_hh + ((bp >= 0) ? (size_t)bp * H : 0) + bu * 8;
    const __nv_bfloat16* xl = g_hl + ((bp >= 0) ? (size_t)bp * H : 0) + bu * 8;

    float4 pv0 = *(const float4*)(wrow + 0);
    float4 pv1 = *(const float4*)(wrow + 4);
    float4 pv2 = *(const float4*)(wrow + 8);
    float4 pv3 = *(const float4*)(wrow + 12);

    float acc[8][4];
#pragma unroll
    for (int i = 0; i < 8; i++) { acc[i][0] = acc[i][1] = acc[i][2] = acc[i][3] = 0.f; }

    uint32_t a_addr = ah_s + (uint32_t)((wid * 16 + (lane & 15)) * 80 + (lane >> 4) * 16);
    int bmi = lane >> 3;
    uint32_t b_off = (uint32_t)(((bmi >> 1) * 8 + (lane & 7)) * 80 + (bmi & 1) * 16);

    cpa16z(bh_s + boff, xh, bok);
    cpa16z(bl_s + boff, xl, bok);
    CPCOMMIT();
    split16(AH, AL, aoff, pv0, pv1, pv2, pv3);
    {
        const float* nx = wrow + 32;
        pv0 = *(const float4*)(nx + 0); pv1 = *(const float4*)(nx + 4);
        pv2 = *(const float4*)(nx + 8); pv3 = *(const float4*)(nx + 12);
    }
    CPWAIT0();
    __syncthreads();

    const int NCH = H / 32;   // 96
    for (int ch = 0; ch < NCH; ch++) {
        int cur = ch & 1, nxt = cur ^ 1;
        if (ch + 1 < NCH) {
            int k1 = (ch + 1) * 32;
            cpa16z(bh_s + (uint32_t)(nxt * 5120) + boff, xh + k1, bok);
            cpa16z(bl_s + (uint32_t)(nxt * 5120) + boff, xl + k1, bok);
            CPCOMMIT();
        }
#pragma unroll
        for (int ks = 0; ks < 2; ks++) {
            uint32_t ahf[4], alf[4];
            ldsm4(ahf, a_addr + (uint32_t)(cur * 10240) + ks * 32);
            ldsm4(alf, a_addr + 20480u + (uint32_t)(cur * 10240) + ks * 32);
#pragma unroll
            for (int j = 0; j < 4; j++) {
                uint32_t bhf[4], blf[4];
                uint32_t badd = (uint32_t)(cur * 5120 + j * 16 * 80 + ks * 32) + b_off;
                ldsm4(bhf, bh_s + badd);
                ldsm4(blf, bl_s + badd);
                mma_bf16(acc[2 * j], ahf, bhf[0], bhf[1]);
                mma_bf16(acc[2 * j], ahf, blf[0], blf[1]);
                mma_bf16(acc[2 * j], alf, bhf[0], bhf[1]);
                mma_bf16(acc[2 * j + 1], ahf, bhf[2], bhf[3]);
                mma_bf16(acc[2 * j + 1], ahf, blf[2], blf[3]);
                mma_bf16(acc[2 * j + 1], alf, bhf[2], bhf[3]);
            }
        }
        if (ch + 1 < NCH) {
            split16(AH + nxt * 10240, AL + nxt * 10240, aoff, pv0, pv1, pv2, pv3);
            if (ch + 2 < NCH) {
                const float* nx = wrow + (ch + 2) * 32;
                pv0 = *(const float4*)(nx + 0); pv1 = *(const float4*)(nx + 4);
                pv2 = *(const float4*)(nx + 8); pv3 = *(const float4*)(nx + 12);
            }
            CPWAIT0();
        }
        __syncthreads();
    }
    int g = lane >> 2, t4 = lane & 3;
    int ddA = n0 + wid * 16 + g;
    int ddB = ddA + 8;
    float bA = b2[e * D + ddA], bB = b2[e * D + ddB];
#pragma unroll
    for (int nf = 0; nf < 8; nf++) {
        int tok = nf * 8 + t4 * 2;
        if (tok < ctn) {
            int p = plist[tok];
            g_y[(size_t)p * D + ddA] = acc[nf][0] + bA;
            g_y[(size_t)p * D + ddB] = acc[nf][2] + bB;
        }
        if (tok + 1 < ctn) {
            int p = plist[tok + 1];
            g_y[(size_t)p * D + ddA] = acc[nf][1] + bA;
            g_y[(size_t)p * D + ddB] = acc[nf][3] + bB;
        }
    }
}

// ------------------------- kI: combine -------------------------------------
__global__ __launch_bounds__(256) void kI_combine(float* __restrict__ out_y)
{
    int tok = blockIdx.x;
    int tid = threadIdx.x;
    float w0 = g_topw[tok * 2], w1 = g_topw[tok * 2 + 1];
    const float* y0 = &g_y[(size_t)(tok * 2) * D];
    const float* y1 = &g_y[(size_t)(tok * 2 + 1) * D];
    for (int dd = tid; dd < D; dd += 256)
        out_y[(size_t)tok * D + dd] += w0 * y0[dd] + w1 * y1[dd];
}

// ------------------------- launch ------------------------------------------
extern "C" void kernel_launch(void* const* d_in, const int* in_sizes, int n_in,
                              void* d_out, int out_size)
{
    (void)in_sizes; (void)n_in; (void)out_size;
    const float* hidden = (const float*)d_in[0];
    const float* probe  = (const float*)d_in[1];
    const float* ipw    = (const float*)d_in[2];
    const float* ipb    = (const float*)d_in[3];
    const float* opw    = (const float*)d_in[4];
    const float* opb    = (const float*)d_in[5];
    const float* lnw    = (const float*)d_in[6];
    const float* lnb    = (const float*)d_in[7];
    const float* gw     = (const float*)d_in[8];
    const float* w1     = (const float*)d_in[9];
    const float* b1     = (const float*)d_in[10];
    const float* w2     = (const float*)d_in[11];
    const float* b2     = (const float*)d_in[12];
    float* out = (float*)d_out;

    cudaFuncSetAttribute(kB_scores_mma, cudaFuncAttributeMaxDynamicSharedMemorySize, KB_SMEM);
    cudaFuncSetAttribute(kD_pooled_mma, cudaFuncAttributeMaxDynamicSharedMemorySize, KD_SMEM);
    cudaFuncSetAttribute(kG_fc1_mma, cudaFuncAttributeMaxDynamicSharedMemorySize, GM_SMEM);
    cudaFuncSetAttribute(kH_fc2_mma, cudaFuncAttributeMaxDynamicSharedMemorySize, GM_SMEM);

    const int OFF_LOSS = B * T * D;        // 196608
    const int OFF_AW   = OFF_LOSS + 1;     // 196609

    kA_qtilde<<<NT, 256>>>(probe, ipw, ipb);
    kB_scores_mma<<<dim3(S / 128, B), 256, KB_SMEM>>>(hidden);
    kC_softmax<<<NTOK, 384>>>(out + OFF_AW);
    kD_pooled_mma<<<dim3(D / 128, B), 256, KD_SMEM>>>(hidden);
    kE1_vproj_mma<<<dim3(NH, 4), 256>>>(ipw, ipb);
    kE2_outproj<<<dim3(6, 8), 256>>>(opw, opb, out);
    kE3_ln_gate<<<NTOK, 256>>>(lnw, lnb, gw);
    kF_route<<<1, 256>>>(out + OFF_LOSS);
    kG_fc1_mma<<<dim3(H / 128, E, 4), 256, GM_SMEM>>>(w1, b1);
    kH_fc2_mma<<<dim3(D / 128, E, 4), 256, GM_SMEM>>>(w2, b2);
    kI_combine<<<NTOK, 256>>>(out);
}

// round 17
// speedup vs baseline: 1.1671x; 1.1377x over previous
#include <cuda_runtime.h>
#include <cuda_bf16.h>
#include <math.h>
#include <stdint.h>

#define B 64
#define S 1024
#define D 768
#define T 4
#define E 8
#define TOPK 2
#define H 3072
#define NH 12
#define HD 64
#define NT 48          // NH*T
#define NTOK 256       // B*T
#define NPAIR 512      // NTOK*TOPK
#define KHP 4          // kH k-parts

// ---------------- packed f32x2 helpers (FFMA2) ------------------------------
typedef unsigned long long f32x2;
__device__ __forceinline__ void fma2(f32x2& c, f32x2 a, f32x2 b) {
    asm("fma.rn.f32x2 %0,%1,%2,%0;" : "+l"(c) : "l"(a), "l"(b));
}
__device__ __forceinline__ float2 unpk(f32x2 v) {
    float2 r; asm("mov.b64 {%0,%1},%2;" : "=f"(r.x), "=f"(r.y) : "l"(v)); return r;
}
__device__ __forceinline__ f32x2 dup2(float v) {
    f32x2 r; asm("mov.b64 %0,{%1,%1};" : "=l"(r) : "f"(v)); return r;
}

// ---------------- cp.async helpers -----------------------------------------
__device__ __forceinline__ uint32_t sptr(const void* p) {
    return (uint32_t)__cvta_generic_to_shared(p);
}
__device__ __forceinline__ void cpa16(uint32_t dst, const void* src) {
    asm volatile("cp.async.ca.shared.global [%0], [%1], 16;" :: "r"(dst), "l"(src));
}
__device__ __forceinline__ void cpa16z(uint32_t dst, const void* src, int sz) {
    asm volatile("cp.async.ca.shared.global [%0], [%1], 16, %2;" :: "r"(dst), "l"(src), "r"(sz));
}
#define CPCOMMIT() asm volatile("cp.async.commit_group;")
#define CPWAIT0()  asm volatile("cp.async.wait_group 0;")

// ---------------- warp MMA helpers (HMMA path, plain sm_103-safe) ----------
__device__ __forceinline__ void ldsm4(uint32_t* r, uint32_t addr) {
    asm volatile("ldmatrix.sync.aligned.m8n8.x4.shared.b16 {%0,%1,%2,%3}, [%4];"
        : "=r"(r[0]), "=r"(r[1]), "=r"(r[2]), "=r"(r[3]) : "r"(addr));
}
__device__ __forceinline__ void mma_bf16(float* c, const uint32_t* a, uint32_t b0, uint32_t b1) {
    asm volatile("mma.sync.aligned.m16n8k16.row.col.f32.bf16.bf16.f32 "
        "{%0,%1,%2,%3},{%4,%5,%6,%7},{%8,%9},{%0,%1,%2,%3};"
        : "+f"(c[0]), "+f"(c[1]), "+f"(c[2]), "+f"(c[3])
        : "r"(a[0]), "r"(a[1]), "r"(a[2]), "r"(a[3]), "r"(b0), "r"(b1));
}
// bf16 split helpers
__device__ __forceinline__ uint32_t cvt_bf2(float hi_elem, float lo_elem) {
    uint32_t r; asm("cvt.rn.bf16x2.f32 %0, %1, %2;" : "=r"(r) : "f"(hi_elem), "f"(lo_elem));
    return r;
}
__device__ __forceinline__ float bflo_f(uint32_t w) { return __uint_as_float(w << 16); }
__device__ __forceinline__ float bfhi_f(uint32_t w) { return __uint_as_float(w & 0xffff0000u); }

// split 16 fp32 -> bf16 hi/lo, store 2x uint4 to each of H and L at off
__device__ __forceinline__ void split16(uint8_t* Hb, uint8_t* Lb, int off,
    float4 v0, float4 v1, float4 v2, float4 v3)
{
    uint32_t h0 = cvt_bf2(v0.y, v0.x), h1 = cvt_bf2(v0.w, v0.z);
    uint32_t h2 = cvt_bf2(v1.y, v1.x), h3 = cvt_bf2(v1.w, v1.z);
    uint32_t h4 = cvt_bf2(v2.y, v2.x), h5 = cvt_bf2(v2.w, v2.z);
    uint32_t h6 = cvt_bf2(v3.y, v3.x), h7 = cvt_bf2(v3.w, v3.z);
    uint32_t l0 = cvt_bf2(v0.y - bfhi_f(h0), v0.x - bflo_f(h0));
    uint32_t l1 = cvt_bf2(v0.w - bfhi_f(h1), v0.z - bflo_f(h1));
    uint32_t l2 = cvt_bf2(v1.y - bfhi_f(h2), v1.x - bflo_f(h2));
    uint32_t l3 = cvt_bf2(v1.w - bfhi_f(h3), v1.z - bflo_f(h3));
    uint32_t l4 = cvt_bf2(v2.y - bfhi_f(h4), v2.x - bflo_f(h4));
    uint32_t l5 = cvt_bf2(v2.w - bfhi_f(h5), v2.z - bflo_f(h5));
    uint32_t l6 = cvt_bf2(v3.y - bfhi_f(h6), v3.x - bflo_f(h6));
    uint32_t l7 = cvt_bf2(v3.w - bfhi_f(h7), v3.z - bflo_f(h7));
    *(uint4*)(Hb + off)      = make_uint4(h0, h1, h2, h3);
    *(uint4*)(Hb + off + 16) = make_uint4(h4, h5, h6, h7);
    *(uint4*)(Lb + off)      = make_uint4(l0, l1, l2, l3);
    *(uint4*)(Lb + off + 16) = make_uint4(l4, l5, l6, l7);
}
// split 8 fp32 -> one uint4 each
__device__ __forceinline__ void split8(uint8_t* Hb, uint8_t* Lb, int off,
    float4 v0, float4 v1)
{
    uint32_t h0 = cvt_bf2(v0.y, v0.x), h1 = cvt_bf2(v0.w, v0.z);
    uint32_t h2 = cvt_bf2(v1.y, v1.x), h3 = cvt_bf2(v1.w, v1.z);
    uint32_t l0 = cvt_bf2(v0.y - bfhi_f(h0), v0.x - bflo_f(h0));
    uint32_t l1 = cvt_bf2(v0.w - bfhi_f(h1), v0.z - bflo_f(h1));
    uint32_t l2 = cvt_bf2(v1.y - bfhi_f(h2), v1.x - bflo_f(h2));
    uint32_t l3 = cvt_bf2(v1.w - bfhi_f(h3), v1.z - bflo_f(h3));
    *(uint4*)(Hb + off) = make_uint4(h0, h1, h2, h3);
    *(uint4*)(Lb + off) = make_uint4(l0, l1, l2, l3);
}

// ------------------------- scratch (device globals) -------------------------
__device__ __align__(16) __nv_bfloat16 g_qth[NT * D];
__device__ __align__(16) __nv_bfloat16 g_qtl[NT * D];
__device__ float g_qb[NT];
__device__ __align__(16) float g_scores[(size_t)B * NT * S];
__device__ __align__(16) __nv_bfloat16 g_ath[(size_t)B * NT * S];
__device__ __align__(16) __nv_bfloat16 g_atl[(size_t)B * NT * S];
__device__ __align__(16) float g_pooled[(size_t)B * NT * D];
__device__ __align__(16) float g_ctx[NTOK * D];
__device__ __align__(16) float g_ao[NTOK * D];
__device__ __align__(16) __nv_bfloat16 g_xlh[NTOK * D];
__device__ __align__(16) __nv_bfloat16 g_xll[NTOK * D];
__device__ __align__(16) __nv_bfloat16 g_hh[(size_t)NPAIR * H];
__device__ __align__(16) __nv_bfloat16 g_hl[(size_t)NPAIR * H];
__device__ float g_probs[NTOK * E];
__device__ int   g_topi[NTOK * TOPK];
__device__ float g_topw[NTOK * TOPK];
__device__ int   g_ecnt[E];
__device__ int   g_elist[E * NPAIR];
__device__ __align__(16) float g_yp[KHP][(size_t)NPAIR * D];   // kH k-part partials

__device__ __forceinline__ float wred(float v) {
#pragma unroll
    for (int o = 16; o > 0; o >>= 1) v += __shfl_down_sync(0xffffffffu, v, o);
    return v;
}
__device__ __forceinline__ float wredmax(float v) {
#pragma unroll
    for (int o = 16; o > 0; o >>= 1) v = fmaxf(v, __shfl_down_sync(0xffffffffu, v, o));
    return v;
}
__device__ __forceinline__ int wredi(int v) {
#pragma unroll
    for (int o = 16; o > 0; o >>= 1) v += __shfl_down_sync(0xffffffffu, v, o);
    return v;
}
__device__ __forceinline__ float gelu_tanh(float x) {
    return 0.5f * x * (1.f + tanhf(0.7978845608028654f * (x + 0.044715f * x * x * x)));
}

// ------------------------- kA: qtilde = (probe@Wq^T + bq) @ Wk --------------
__global__ __launch_bounds__(256) void kA_qtilde(
    const float* __restrict__ probe, const float* __restrict__ ipw,
    const float* __restrict__ ipb)
{
    int ht = blockIdx.x;
    int h = ht >> 2, t = ht & 3;
    __shared__ float q_s[HD];
    int tid = threadIdx.x, lane = tid & 31, warp = tid >> 5;

    for (int j = warp; j < HD; j += 8) {
        int row = h * HD + j;
        const float* w = ipw + (size_t)row * D;
        const float* p = probe + t * D;
        float acc = 0.f;
        for (int dd = lane; dd < D; dd += 32) acc += p[dd] * w[dd];
        acc = wred(acc);
        if (lane == 0) q_s[j] = acc + ipb[row];
    }
    __syncthreads();
    if (tid == 0) {
        float qb = 0.f;
        for (int j = 0; j < HD; j++) qb += q_s[j] * ipb[D + h * HD + j];
        g_qb[ht] = qb;
    }
    for (int dd = tid; dd < D; dd += 256) {
        float acc = 0.f;
        const float* wk = ipw + (size_t)(D + h * HD) * D + dd;
#pragma unroll 8
        for (int j = 0; j < HD; j++) acc += q_s[j] * wk[(size_t)j * D];
        __nv_bfloat16 hb = __float2bfloat16(acc);
        float hf = __bfloat162float(hb);
        g_qth[ht * D + dd] = hb;
        g_qtl[ht * D + dd] = __float2bfloat16(acc - hf);
    }
}

// ------------------------- kB: scores, double-buffered, k-split warps -------
#define KB_SMEM 56512
__global__ __launch_bounds__(256, 2) void kB_scores_mma(const float* __restrict__ hidden)
{
    extern __shared__ __align__(16) uint8_t dsm[];
    uint8_t* AH = dsm;
    uint8_t* AL = dsm + 20480;
    float* qbs = (float*)(dsm + 56320);
    uint32_t base = sptr(dsm);
    uint32_t ah_s = base, bh_s = base + 40960, bl_s = base + 48640;

    int b = blockIdx.y;
    int s0 = blockIdx.x * 128;
    int tid = threadIdx.x, lane = tid & 31, wid = tid >> 5;
    int wq = wid & 3, ksw = wid >> 2;
    uint32_t kso = (uint32_t)(ksw * 32);

    if (tid < NT) qbs[tid] = g_qb[tid];

    int arow = tid & 127, ahalf = tid >> 7;
    const float* hrow = hidden + ((size_t)b * S + s0 + arow) * D + ahalf * 16;
    int aoff = arow * 80 + ahalf * 32;
    int brow = tid >> 2, bu = tid & 3;
    uint32_t boff = (uint32_t)(brow * 80 + bu * 16);

    float4 pv0 = *(const float4*)(hrow + 0);
    float4 pv1 = *(const float4*)(hrow + 4);
    float4 pv2 = *(const float4*)(hrow + 8);
    float4 pv3 = *(const float4*)(hrow + 12);

    float acc[2][6][4];
#pragma unroll
    for (int s = 0; s < 2; s++)
#pragma unroll
        for (int i = 0; i < 6; i++) { acc[s][i][0] = acc[s][i][1] = acc[s][i][2] = acc[s][i][3] = 0.f; }

    uint32_t a_addr = ah_s + (uint32_t)((wq * 32 + (lane & 15)) * 80 + (lane >> 4) * 16);
    int bmi = lane >> 3;
    uint32_t b_off = (uint32_t)(((bmi >> 1) * 8 + (lane & 7)) * 80 + (bmi & 1) * 16);

    if (tid < 192) {
        cpa16(bh_s + boff, g_qth + (size_t)brow * D + bu * 8);
        cpa16(bl_s + boff, g_qtl + (size_t)brow * D + bu * 8);
    }
    CPCOMMIT();
    split16(AH, AL, aoff, pv0, pv1, pv2, pv3);
    {
        const float* nx = hrow + 32;
        pv0 = *(const float4*)(nx + 0); pv1 = *(const float4*)(nx + 4);
        pv2 = *(const float4*)(nx + 8); pv3 = *(const float4*)(nx + 12);
    }
    CPWAIT0();
    __syncthreads();

    const int NCH = D / 32;   // 24
    for (int ch = 0; ch < NCH; ch++) {
        int cur = ch & 1, nxt = cur ^ 1;
        if (ch + 1 < NCH) {
            int k1 = (ch + 1) * 32;
            if (tid < 192) {
                cpa16(bh_s + (uint32_t)(nxt * 3840) + boff, g_qth + (size_t)brow * D + k1 + bu * 8);
                cpa16(bl_s + (uint32_t)(nxt * 3840) + boff, g_qtl + (size_t)brow * D + k1 + bu * 8);
            }
            CPCOMMIT();
        }
        {
            uint32_t bhf[12], blf[12];
#pragma unroll
            for (int j = 0; j < 3; j++) {
                uint32_t badd = (uint32_t)(cur * 3840 + j * 16 * 80) + b_off + kso;
                ldsm4(bhf + 4 * j, bh_s + badd);
                ldsm4(blf + 4 * j, bl_s + badd);
            }
#pragma unroll
            for (int s = 0; s < 2; s++) {
                uint32_t ahf[4], alf[4];
                uint32_t aadd = a_addr + (uint32_t)(cur * 10240 + s * 1280) + kso;
                ldsm4(ahf, aadd);
                ldsm4(alf, aadd + 20480u);
#pragma unroll
                for (int j = 0; j < 3; j++) {
                    mma_bf16(acc[s][2 * j], ahf, bhf[4 * j], bhf[4 * j + 1]);
                    mma_bf16(acc[s][2 * j], ahf, blf[4 * j], blf[4 * j + 1]);
                    mma_bf16(acc[s][2 * j], alf, bhf[4 * j], bhf[4 * j + 1]);
                    mma_bf16(acc[s][2 * j + 1], ahf, bhf[4 * j + 2], bhf[4 * j + 3]);
                    mma_bf16(acc[s][2 * j + 1], ahf, blf[4 * j + 2], blf[4 * j + 3]);
                    mma_bf16(acc[s][2 * j + 1], alf, bhf[4 * j + 2], bhf[4 * j + 3]);
                }
            }
        }
        if (ch + 1 < NCH) {
            split16(AH + nxt * 10240, AL + nxt * 10240, aoff, pv0, pv1, pv2, pv3);
            if (ch + 2 < NCH) {
                const float* nx = hrow + (ch + 2) * 32;
                pv0 = *(const float4*)(nx + 0); pv1 = *(const float4*)(nx + 4);
                pv2 = *(const float4*)(nx + 8); pv3 = *(const float4*)(nx + 12);
            }
            CPWAIT0();
        }
        __syncthreads();
    }
    float* red = (float*)dsm;
    if (ksw == 1) {
        float* dst = red + (size_t)(wq * 32 + lane) * 48;
#pragma unroll
        for (int s = 0; s < 2; s++)
#pragma unroll
            for (int i = 0; i < 6; i++)
#pragma unroll
                for (int f = 0; f < 4; f++) dst[(s * 6 + i) * 4 + f] = acc[s][i][f];
    }
    __syncthreads();
    if (ksw == 0) {
        const float* src = red + (size_t)(wq * 32 + lane) * 48;
        int g = lane >> 2, t4 = lane & 3;
        float* outb = g_scores + (size_t)b * NT * S;
#pragma unroll
        for (int s = 0; s < 2; s++) {
            int srow = s0 + (wq * 2 + s) * 16 + g;
#pragma unroll
            for (int nf = 0; nf < 6; nf++) {
                int n0 = nf * 8 + t4 * 2;
                float c0 = acc[s][nf][0] + src[(s * 6 + nf) * 4 + 0];
                float c1 = acc[s][nf][1] + src[(s * 6 + nf) * 4 + 1];
                float c2 = acc[s][nf][2] + src[(s * 6 + nf) * 4 + 2];
                float c3 = acc[s][nf][3] + src[(s * 6 + nf) * 4 + 3];
                outb[(size_t)n0 * S + srow]           = 0.125f * (c0 + qbs[n0]);
                outb[(size_t)(n0 + 1) * S + srow]     = 0.125f * (c1 + qbs[n0 + 1]);
                outb[(size_t)n0 * S + srow + 8]       = 0.125f * (c2 + qbs[n0]);
                outb[(size_t)(n0 + 1) * S + srow + 8] = 0.125f * (c3 + qbs[n0 + 1]);
            }
        }
    }
}

// ------------------------- kC: softmax + head-mean; write attn bf16 hi/lo ---
__global__ __launch_bounds__(384) void kC_softmax(float* __restrict__ out_aw)
{
    int bt = blockIdx.x, b = bt >> 2, t = bt & 3;
    __shared__ float stage[NH][S];
    int tid = threadIdx.x, lane = tid & 31, warp = tid >> 5;

    size_t rowoff = ((size_t)b * NT + warp * T + t) * S;
    const float* row = g_scores + rowoff;
    float4 v[8];
#pragma unroll
    for (int i = 0; i < 8; i++) v[i] = *(const float4*)(row + i * 128 + lane * 4);
    float m = -1e30f;
#pragma unroll
    for (int i = 0; i < 8; i++)
        m = fmaxf(m, fmaxf(fmaxf(v[i].x, v[i].y), fmaxf(v[i].z, v[i].w)));
    m = wredmax(m);
    m = __shfl_sync(0xffffffffu, m, 0);
    float sum = 0.f;
#pragma unroll
    for (int i = 0; i < 8; i++) {
        v[i].x = __expf(v[i].x - m); v[i].y = __expf(v[i].y - m);
        v[i].z = __expf(v[i].z - m); v[i].w = __expf(v[i].w - m);
        sum += v[i].x + v[i].y + v[i].z + v[i].w;
    }
    sum = wred(sum);
    float inv = 1.f / __shfl_sync(0xffffffffu, sum, 0);
#pragma unroll
    for (int i = 0; i < 8; i++) {
        v[i].x *= inv; v[i].y *= inv; v[i].z *= inv; v[i].w *= inv;
        *(float4*)&stage[warp][i * 128 + lane * 4] = v[i];
        uint32_t h0 = cvt_bf2(v[i].y, v[i].x), h1 = cvt_bf2(v[i].w, v[i].z);
        uint32_t l0 = cvt_bf2(v[i].y - bfhi_f(h0), v[i].x - bflo_f(h0));
        uint32_t l1 = cvt_bf2(v[i].w - bfhi_f(h1), v[i].z - bflo_f(h1));
        size_t idx = rowoff + i * 128 + lane * 4;
        *(uint2*)&g_ath[idx] = make_uint2(h0, h1);
        *(uint2*)&g_atl[idx] = make_uint2(l0, l1);
    }
    __syncthreads();
    const float inv12 = 1.f / 12.f;
#pragma unroll
    for (int r = 0; r < 3; r++) {
        int s = tid + 384 * r;
        if (s < S) {
            float a = 0.f;
#pragma unroll
            for (int h = 0; h < NH; h++) a += stage[h][s];
            out_aw[(size_t)bt * S + s] = a * inv12;
        }
    }
}

// ------------------------- kD: pooled, cp.async A, 3 CTAs/SM ----------------
#define KD_SMEM 56320
__global__ __launch_bounds__(256, 3) void kD_pooled_mma(const float* __restrict__ hidden)
{
    extern __shared__ __align__(16) uint8_t dsm[];
    uint8_t* BH = dsm + 15360;
    uint8_t* BL = dsm + 35840;
    uint32_t base = sptr(dsm);
    uint32_t ah_s = base, al_s = base + 7680, bh_s = base + 15360, bl_s = base + 35840;

    int b = blockIdx.y;
    int n0 = blockIdx.x * 128;
    int tid = threadIdx.x, lane = tid & 31, wid = tid >> 5;

    int am = tid >> 2, au = tid & 3;
    size_t arowo = ((size_t)b * NT + (am < NT ? am : 0)) * S + au * 8;
    uint32_t a_stoff = (uint32_t)(am * 80 + au * 16);

    int bn = tid & 127, bkg = tid >> 7;
    const float* hcol = hidden + ((size_t)b * S + bkg * 16) * D + n0 + bn;
    int b_st = bn * 80 + bkg * 32;

    float hb0[8];
#pragma unroll
    for (int j = 0; j < 8; j++) hb0[j] = hcol[(size_t)j * D];

    float acc[3][2][4];
#pragma unroll
    for (int i = 0; i < 3; i++)
#pragma unroll
        for (int f = 0; f < 2; f++) { acc[i][f][0] = acc[i][f][1] = acc[i][f][2] = acc[i][f][3] = 0.f; }

    uint32_t aA[3];
#pragma unroll
    for (int st = 0; st < 3; st++)
        aA[st] = ah_s + (uint32_t)((st * 16 + (lane & 15)) * 80 + (lane >> 4) * 16);
    int bmi = lane >> 3;
    uint32_t b_off = (uint32_t)((wid * 16 + (bmi >> 1) * 8 + (lane & 7)) * 80 + (bmi & 1) * 16);

    if (tid < 192) {
        cpa16(ah_s + a_stoff, g_ath + arowo);
        cpa16(al_s + a_stoff, g_atl + arowo);
    }
    CPCOMMIT();
    split8(dsm + 15360, dsm + 35840, b_st,
           make_float4(hb0[0], hb0[1], hb0[2], hb0[3]),
           make_float4(hb0[4], hb0[5], hb0[6], hb0[7]));
    {
        float4 q0 = make_float4(hcol[8 * (size_t)D], hcol[9 * (size_t)D], hcol[10 * (size_t)D], hcol[11 * (size_t)D]);
        float4 q1 = make_float4(hcol[12 * (size_t)D], hcol[13 * (size_t)D], hcol[14 * (size_t)D], hcol[15 * (size_t)D]);
        split8(BH, BL, b_st + 16, q0, q1);
    }
#pragma unroll
    for (int j = 0; j < 8; j++) hb0[j] = hcol[(size_t)(32 + j) * D];
    CPWAIT0();
    __syncthreads();

    const int NCH = S / 32;   // 32
    for (int ch = 0; ch < NCH; ch++) {
        int cur = ch & 1, nxt = cur ^ 1;
        if (ch + 1 < NCH) {
            int k1 = (ch + 1) * 32;
            if (tid < 192) {
                cpa16(ah_s + (uint32_t)(nxt * 3840) + a_stoff, g_ath + arowo + k1);
                cpa16(al_s + (uint32_t)(nxt * 3840) + a_stoff, g_atl + arowo + k1);
            }
            CPCOMMIT();
        }
#pragma unroll
        for (int ks = 0; ks < 2; ks++) {
            uint32_t bhf[4], blf[4];
            ldsm4(bhf, bh_s + (uint32_t)(cur * 10240) + b_off + ks * 32);
            ldsm4(blf, bl_s + (uint32_t)(cur * 10240) + b_off + ks * 32);
#pragma unroll
            for (int st = 0; st < 3; st++) {
                uint32_t ahf[4], alf[4];
                uint32_t aadd = aA[st] + (uint32_t)(cur * 3840) + ks * 32;
                ldsm4(ahf, aadd);
                ldsm4(alf, aadd + 7680u);
                mma_bf16(acc[st][0], ahf, bhf[0], bhf[1]);
                mma_bf16(acc[st][0], ahf, blf[0], blf[1]);
                mma_bf16(acc[st][0], alf, bhf[0], bhf[1]);
                mma_bf16(acc[st][1], ahf, bhf[2], bhf[3]);
                mma_bf16(acc[st][1], ahf, blf[2], blf[3]);
                mma_bf16(acc[st][1], alf, bhf[2], bhf[3]);
            }
        }
        if (ch + 1 < NCH) {
            int k1 = (ch + 1) * 32;
            split8(BH + nxt * 10240, BL + nxt * 10240, b_st,
                   make_float4(hb0[0], hb0[1], hb0[2], hb0[3]),
                   make_float4(hb0[4], hb0[5], hb0[6], hb0[7]));
            {
                const float* hc = hcol + (size_t)k1 * D;
                float4 q0 = make_float4(hc[8 * (size_t)D], hc[9 * (size_t)D], hc[10 * (size_t)D], hc[11 * (size_t)D]);
                float4 q1 = make_float4(hc[12 * (size_t)D], hc[13 * (size_t)D], hc[14 * (size_t)D], hc[15 * (size_t)D]);
                split8(BH + nxt * 10240, BL + nxt * 10240, b_st + 16, q0, q1);
            }
            if (ch + 2 < NCH) {
                int k2 = (ch + 2) * 32;
                const float* hc2 = hcol + (size_t)k2 * D;
#pragma unroll
                for (int j = 0; j < 8; j++) hb0[j] = hc2[(size_t)j * D];
            }
            CPWAIT0();
        }
        __syncthreads();
    }
    int g = lane >> 2, t4 = lane & 3;
#pragma unroll
    for (int st = 0; st < 3; st++) {
        int m = st * 16 + g;
        float* base0 = g_pooled + ((size_t)b * NT + m) * D + n0;
        float* base1 = g_pooled + ((size_t)b * NT + m + 8) * D + n0;
#pragma unroll
        for (int f = 0; f < 2; f++) {
            int n = wid * 16 + f * 8 + t4 * 2;
            base0[n]     = acc[st][f][0];
            base0[n + 1] = acc[st][f][1];
            base1[n]     = acc[st][f][2];
            base1[n + 1] = acc[st][f][3];
        }
    }
}

// ------------------------- kE1: v-proj via mma.sync bf16-split --------------
__global__ __launch_bounds__(256, 2) void kE1_vproj_mma(
    const float* __restrict__ ipw, const float* __restrict__ ipb)
{
    __shared__ __align__(16) uint8_t AH[64 * 80];
    __shared__ __align__(16) uint8_t AL[64 * 80];
    __shared__ __align__(16) uint8_t BH[64 * 80];
    __shared__ __align__(16) uint8_t BL[64 * 80];

    int h = blockIdx.x;
    int tok0 = blockIdx.y * 64;
    int tid = threadIdx.x, lane = tid & 31, wid = tid >> 5;
    int st = wid & 3, nh = wid >> 2;

    uint32_t ah_s = sptr(AH), al_s = sptr(AL), bh_s = sptr(BH), bl_s = sptr(BL);

    int arow = tid >> 2, aq = tid & 3;
    const float* wrow = ipw + (size_t)(2 * D + h * HD + arow) * D + aq * 8;
    int tk = tok0 + (tid >> 2);
    const float* prow = g_pooled + ((size_t)(tk >> 2) * NT + h * T + (tk & 3)) * D + aq * 8;

    float4 pa0 = *(const float4*)wrow, pa1 = *(const float4*)(wrow + 4);
    float4 pb0 = *(const float4*)prow, pb1 = *(const float4*)(prow + 4);

    float acc[4][4];
#pragma unroll
    for (int i = 0; i < 4; i++) { acc[i][0] = acc[i][1] = acc[i][2] = acc[i][3] = 0.f; }

    uint32_t a_addr = ah_s + (uint32_t)((st * 16 + (lane & 15)) * 80 + (lane >> 4) * 16);
    uint32_t al_addr = a_addr + (al_s - ah_s);
    int bmi = lane >> 3;
    uint32_t b_off = (uint32_t)((nh * 32 + (bmi >> 1) * 8 + (lane & 7)) * 80 + (bmi & 1) * 16);

    const int NCH = D / 32;
    for (int ch = 0; ch < NCH; ch++) {
        {
            int off = arow * 80 + aq * 16;
            split8(AH, AL, off, pa0, pa1);
            split8(BH, BL, off, pb0, pb1);
        }
        __syncthreads();
        if (ch + 1 < NCH) {
            int k1 = (ch + 1) * 32;
            pa0 = *(const float4*)(wrow + k1);
            pa1 = *(const float4*)(wrow + k1 + 4);
            pb0 = *(const float4*)(prow + k1);
            pb1 = *(const float4*)(prow + k1 + 4);
        }
#pragma unroll
        for (int ks = 0; ks < 2; ks++) {
            uint32_t ahf[4], alf[4];
            ldsm4(ahf, a_addr + ks * 32);
            ldsm4(alf, al_addr + ks * 32);
#pragma unroll
            for (int j = 0; j < 2; j++) {
                uint32_t bhf[4], blf[4];
                uint32_t badd = (uint32_t)(j * 16 * 80 + ks * 32) + b_off;
                ldsm4(bhf, bh_s + badd);
                ldsm4(blf, bl_s + badd);
                mma_bf16(acc[2 * j], ahf, bhf[0], bhf[1]);
                mma_bf16(acc[2 * j], ahf, blf[0], blf[1]);
                mma_bf16(acc[2 * j], alf, bhf[0], bhf[1]);
                mma_bf16(acc[2 * j + 1], ahf, bhf[2], bhf[3]);
                mma_bf16(acc[2 * j + 1], ahf, blf[2], blf[3]);
                mma_bf16(acc[2 * j + 1], alf, bhf[2], bhf[3]);
            }
        }
        __syncthreads();
    }
    int g = lane >> 2, t4 = lane & 3;
    int jA = h * HD + st * 16 + g;
    int jB = jA + 8;
    float bA = ipb[2 * D + jA], bB = ipb[2 * D + jB];
#pragma unroll
    for (int nf = 0; nf < 4; nf++) {
        int tkc = tok0 + nh * 32 + nf * 8 + t4 * 2;
        g_ctx[(size_t)tkc * D + jA]       = acc[nf][0] + bA;
        g_ctx[(size_t)(tkc + 1) * D + jA] = acc[nf][1] + bA;
        g_ctx[(size_t)tkc * D + jB]       = acc[nf][2] + bB;
        g_ctx[(size_t)(tkc + 1) * D + jB] = acc[nf][3] + bB;
    }
}

// ------------------------- kE2: out-proj GEMM + residual --------------------
__global__ __launch_bounds__(256) void kE2_outproj(
    const float* __restrict__ opw, const float* __restrict__ opb,
    float* __restrict__ out_y)
{
    int r0 = blockIdx.x * 128;
    int t0 = blockIdx.y * 32;
    __shared__ __align__(16) float cs[32 * 17];
    __shared__ __align__(16) float ws[16 * 132 + 16];
    int tid = threadIdx.x;
    int tr = tid & 31;
    int tt = tid >> 5;
    f32x2 acc[4][2];
#pragma unroll
    for (int t = 0; t < 4; t++) { acc[t][0] = 0ull; acc[t][1] = 0ull; }

    for (int k0 = 0; k0 < D; k0 += 16) {
#pragma unroll
        for (int r = 0; r < 2; r++) {
            int idx = tid + 256 * r;
            int tok = idx >> 4, kk = idx & 15;
            cs[tok * 17 + kk] = g_ctx[(size_t)(t0 + tok) * D + k0 + kk];
        }
#pragma unroll
        for (int r = 0; r < 2; r++) {
            int idx = tid + 256 * r;
            int rr = idx >> 2, ko = (idx & 3) << 2;
            float4 v = *(const float4*)(opw + (size_t)(r0 + rr) * D + k0 + ko);
            float* base = &ws[ko * 132 + rr + ko];
            base[0] = v.x; base[132] = v.y; base[264] = v.z; base[396] = v.w;
        }
        __syncthreads();
#pragma unroll 4
        for (int kk = 0; kk < 16; kk++) {
            ulonglong2 wu = *(const ulonglong2*)(&ws[kk * 132 + (kk & 12)] + tr * 4);
#pragma unroll
            for (int t = 0; t < 4; t++) {
                f32x2 ad = dup2(cs[(tt * 4 + t) * 17 + kk]);
                fma2(acc[t][0], wu.x, ad);
                fma2(acc[t][1], wu.y, ad);
            }
        }
        __syncthreads();
    }
    float4 bb = *(const float4*)&opb[r0 + tr * 4];
#pragma unroll
    for (int t = 0; t < 4; t++) {
        int tok = t0 + tt * 4 + t;
        float2 u0 = unpk(acc[t][0]), u1 = unpk(acc[t][1]);
        float4 o = make_float4(u0.x + bb.x, u0.y + bb.y, u1.x + bb.z, u1.y + bb.w);
        *(float4*)&out_y[(size_t)tok * D + r0 + tr * 4] = o;
        *(float4*)&g_ao[(size_t)tok * D + r0 + tr * 4] = o;
    }
}

// ------------------------- kE3: LN + gate + top2, per token -----------------
__global__ __launch_bounds__(256) void kE3_ln_gate(
    const float* __restrict__ lnw, const float* __restrict__ lnb,
    const float* __restrict__ gw)
{
    int tok = blockIdx.x;
    int t = tok & 3;
    __shared__ float x[D];
    __shared__ float red[256];
    __shared__ float lg[E];
    int tid = threadIdx.x, lane = tid & 31, warp = tid >> 5;

    float v0 = g_ao[(size_t)tok * D + tid];
    float v1 = g_ao[(size_t)tok * D + tid + 256];
    float v2 = g_ao[(size_t)tok * D + tid + 512];
    red[tid] = v0 + v1 + v2; __syncthreads();
    for (int o = 128; o > 0; o >>= 1) { if (tid < o) red[tid] += red[tid + o]; __syncthreads(); }
    float mu = red[0] * (1.f / 768.f); __syncthreads();
    float d0 = v0 - mu, d1 = v1 - mu, d2 = v2 - mu;
    red[tid] = d0 * d0 + d1 * d1 + d2 * d2; __syncthreads();
    for (int o = 128; o > 0; o >>= 1) { if (tid < o) red[tid] += red[tid + o]; __syncthreads(); }
    float rstd = rsqrtf(red[0] * (1.f / 768.f) + 1e-6f); __syncthreads();

#pragma unroll
    for (int r = 0; r < 3; r++) {
        int dd = tid + 256 * r;
        float dv = (r == 0) ? d0 : (r == 1) ? d1 : d2;
        float xv = dv * rstd * lnw[dd] + lnb[dd];
        x[dd] = xv;
        __nv_bfloat16 hb = __float2bfloat16(xv);
        g_xlh[(size_t)tok * D + dd] = hb;
        g_xll[(size_t)tok * D + dd] = __float2bfloat16(xv - __bfloat162float(hb));
    }
    __syncthreads();

    if (warp < E) {
        float acc = 0.f;
        for (int dd = lane; dd < D; dd += 32)
            acc += x[dd] * gw[((size_t)t * D + dd) * E + warp];
        acc = wred(acc);
        if (lane == 0) lg[warp] = acc;
    }
    __syncthreads();
    if (tid == 0) {
        float p[E];
        float mx = lg[0];
        for (int e = 1; e < E; e++) mx = fmaxf(mx, lg[e]);
        float sum = 0.f;
        for (int e = 0; e < E; e++) { p[e] = __expf(lg[e] - mx); sum += p[e]; }
        float inv = 1.f / sum;
        for (int e = 0; e < E; e++) { p[e] *= inv; g_probs[tok * E + e] = p[e]; }
        int i0 = 0;
        for (int e = 1; e < E; e++) if (p[e] > p[i0]) i0 = e;
        int i1 = (i0 == 0) ? 1 : 0;
        for (int e = 0; e < E; e++) if (e != i0 && p[e] > p[i1]) i1 = e;
        float inv2 = 1.f / (p[i0] + p[i1]);
        g_topi[tok * 2] = i0; g_topi[tok * 2 + 1] = i1;
        g_topw[tok * 2] = p[i0] * inv2; g_topw[tok * 2 + 1] = p[i1] * inv2;
    }
}

// ------------------------- kF: routing lists + moe_loss ---------------------
__global__ __launch_bounds__(256) void kF_route(float* __restrict__ out_loss)
{
    __shared__ int ti[NPAIR];
    __shared__ float imp_s[E];
    __shared__ int disp_s[E];
    int tid = threadIdx.x, lane = tid & 31, warp = tid >> 5;
    for (int i = tid; i < NPAIR; i += 256) ti[i] = g_topi[i];
    __syncthreads();
    if (warp < E) {
        float acc = 0.f;
        for (int tok = lane; tok < NTOK; tok += 32) acc += g_probs[tok * E + warp];
        int cnt = 0;
        for (int p = lane; p < NPAIR; p += 32) cnt += (ti[p] == warp);
        acc = wred(acc); cnt = wredi(cnt);
        if (lane == 0) { imp_s[warp] = acc * (1.f / NTOK); disp_s[warp] = cnt; }
    }
    __syncthreads();
    if (tid == 0) {
        float loss = 0.f;
        for (int e = 0; e < E; e++) loss += imp_s[e] * ((float)disp_s[e] * (1.f / NTOK));
        out_loss[0] = (float)E * loss;
    }
    if (tid < E) {
        int c = 0;
        for (int p = 0; p < NPAIR; p++)
            if (ti[p] == tid) g_elist[tid * NPAIR + (c++)] = p;
        g_ecnt[tid] = c;
    }
}

// ------------------------- kG: fc1 + gelu, double-buffered -------------------
#define GM_SMEM 61696
#define GM_CH 64
__global__ __launch_bounds__(256, 2) void kG_fc1_mma(
    const float* __restrict__ w1, const float* __restrict__ b1)
{
    extern __shared__ __align__(16) uint8_t dsm[];
    uint8_t* AH = dsm;
    uint8_t* AL = dsm + 20480;
    int* plist = (int*)(dsm + 61440);
    uint32_t base = sptr(dsm);
    uint32_t ah_s = base, bh_s = base + 40960, bl_s = base + 51200;

    int h0 = blockIdx.x * 128;
    int e = blockIdx.y;
    int c0 = blockIdx.z * GM_CH;
    int nt = g_ecnt[e];
    if (c0 >= nt) return;
    int ctn = min(GM_CH, nt - c0);
    int tid = threadIdx.x, lane = tid & 31, wid = tid >> 5;
    if (tid < GM_CH) plist[tid] = (tid < ctn) ? g_elist[e * NPAIR + c0 + tid] : -1;
    __syncthreads();

    int arow = tid & 127, ahalf = tid >> 7;
    const float* wrow = w1 + ((size_t)e * H + h0 + arow) * D + ahalf * 16;
    int aoff = arow * 80 + ahalf * 32;

    int brow = tid >> 2, bu = tid & 3;
    uint32_t boff = (uint32_t)(brow * 80 + bu * 16);
    int bp = plist[brow];
    int bok = (bp >= 0) ? 16 : 0;
    const __nv_bfloat16* xh = g_xlh + ((bp >= 0) ? (size_t)(bp >> 1) * D : 0) + bu * 8;
    const __nv_bfloat16* xl = g_xll + ((bp >= 0) ? (size_t)(bp >> 1) * D : 0) + bu * 8;

    float4 pv0 = *(const float4*)(wrow + 0);
    float4 pv1 = *(const float4*)(wrow + 4);
    float4 pv2 = *(const float4*)(wrow + 8);
    float4 pv3 = *(const float4*)(wrow + 12);

    float acc[8][4];
#pragma unroll
    for (int i = 0; i < 8; i++) { acc[i][0] = acc[i][1] = acc[i][2] = acc[i][3] = 0.f; }

    uint32_t a_addr = ah_s + (uint32_t)((wid * 16 + (lane & 15)) * 80 + (lane >> 4) * 16);
    int bmi = lane >> 3;
    uint32_t b_off = (uint32_t)(((bmi >> 1) * 8 + (lane & 7)) * 80 + (bmi & 1) * 16);

    cpa16z(bh_s + boff, xh, bok);
    cpa16z(bl_s + boff, xl, bok);
    CPCOMMIT();
    split16(AH, AL, aoff, pv0, pv1, pv2, pv3);
    {
        const float* nx = wrow + 32;
        pv0 = *(const float4*)(nx + 0); pv1 = *(const float4*)(nx + 4);
        pv2 = *(const float4*)(nx + 8); pv3 = *(const float4*)(nx + 12);
    }
    CPWAIT0();
    __syncthreads();

    const int NCH = D / 32;   // 24
    for (int ch = 0; ch < NCH; ch++) {
        int cur = ch & 1, nxt = cur ^ 1;
        if (ch + 1 < NCH) {
            int k1 = (ch + 1) * 32;
            cpa16z(bh_s + (uint32_t)(nxt * 5120) + boff, xh + k1, bok);
            cpa16z(bl_s + (uint32_t)(nxt * 5120) + boff, xl + k1, bok);
            CPCOMMIT();
        }
#pragma unroll
        for (int ks = 0; ks < 2; ks++) {
            uint32_t ahf[4], alf[4];
            ldsm4(ahf, a_addr + (uint32_t)(cur * 10240) + ks * 32);
            ldsm4(alf, a_addr + 20480u + (uint32_t)(cur * 10240) + ks * 32);
#pragma unroll
            for (int j = 0; j < 4; j++) {
                uint32_t bhf[4], blf[4];
                uint32_t badd = (uint32_t)(cur * 5120 + j * 16 * 80 + ks * 32) + b_off;
                ldsm4(bhf, bh_s + badd);
                ldsm4(blf, bl_s + badd);
                mma_bf16(acc[2 * j], ahf, bhf[0], bhf[1]);
                mma_bf16(acc[2 * j], ahf, blf[0], blf[1]);
                mma_bf16(acc[2 * j], alf, bhf[0], bhf[1]);
                mma_bf16(acc[2 * j + 1], ahf, bhf[2], bhf[3]);
                mma_bf16(acc[2 * j + 1], ahf, blf[2], blf[3]);
                mma_bf16(acc[2 * j + 1], alf, bhf[2], bhf[3]);
            }
        }
        if (ch + 1 < NCH) {
            split16(AH + nxt * 10240, AL + nxt * 10240, aoff, pv0, pv1, pv2, pv3);
            if (ch + 2 < NCH) {
                const float* nx = wrow + (ch + 2) * 32;
                pv0 = *(const float4*)(nx + 0); pv1 = *(const float4*)(nx + 4);
                pv2 = *(const float4*)(nx + 8); pv3 = *(const float4*)(nx + 12);
            }
            CPWAIT0();
        }
        __syncthreads();
    }
    int g = lane >> 2, t4 = lane & 3;
    int hhA = h0 + wid * 16 + g;
    int hhB = hhA + 8;
    float bA = b1[e * H + hhA], bB = b1[e * H + hhB];
#pragma unroll
    for (int nf = 0; nf < 8; nf++) {
        int tok = nf * 8 + t4 * 2;
        if (tok < ctn) {
            int p = plist[tok];
            float vA = gelu_tanh(acc[nf][0] + bA);
            float vB = gelu_tanh(acc[nf][2] + bB);
            __nv_bfloat16 ha = __float2bfloat16(vA);
            __nv_bfloat16 hb2 = __float2bfloat16(vB);
            g_hh[(size_t)p * H + hhA] = ha;
            g_hl[(size_t)p * H + hhA] = __float2bfloat16(vA - __bfloat162float(ha));
            g_hh[(size_t)p * H + hhB] = hb2;
            g_hl[(size_t)p * H + hhB] = __float2bfloat16(vB - __bfloat162float(hb2));
        }
        if (tok + 1 < ctn) {
            int p = plist[tok + 1];
            float vA = gelu_tanh(acc[nf][1] + bA);
            float vB = gelu_tanh(acc[nf][3] + bB);
            __nv_bfloat16 ha = __float2bfloat16(vA);
            __nv_bfloat16 hb2 = __float2bfloat16(vB);
            g_hh[(size_t)p * H + hhA] = ha;
            g_hl[(size_t)p * H + hhA] = __float2bfloat16(vA - __bfloat162float(ha));
            g_hh[(size_t)p * H + hhB] = hb2;
            g_hl[(size_t)p * H + hhB] = __float2bfloat16(vB - __bfloat162float(hb2));
        }
    }
}

// ------------------------- kH: fc2, K split into KHP parts ------------------
// grid (D/128, E, 4*KHP): z = chunk*KHP + kpart. Partials -> g_yp[kpart].
__global__ __launch_bounds__(256, 2) void kH_fc2_mma(
    const float* __restrict__ w2, const float* __restrict__ b2)
{
    extern __shared__ __align__(16) uint8_t dsm[];
    uint8_t* AH = dsm;
    uint8_t* AL = dsm + 20480;
    int* plist = (int*)(dsm + 61440);
    uint32_t base = sptr(dsm);
    uint32_t ah_s = base, bh_s = base + 40960, bl_s = base + 51200;

    int n0 = blockIdx.x * 128;
    int e = blockIdx.y;
    int kpart = blockIdx.z & (KHP - 1);
    int c0 = (blockIdx.z >> 2) * GM_CH;
    int nt = g_ecnt[e];
    if (c0 >= nt) return;
    int ctn = min(GM_CH, nt - c0);
    int tid = threadIdx.x, lane = tid & 31, wid = tid >> 5;
    if (tid < GM_CH) plist[tid] = (tid < ctn) ? g_elist[e * NPAIR + c0 + tid] : -1;
    __syncthreads();

    const int kbase = kpart * (H / KHP);   // 768 per part

    int arow = tid & 127, ahalf = tid >> 7;
    const float* wrow = w2 + ((size_t)e * D + n0 + arow) * H + kbase + ahalf * 16;
    int aoff = arow * 80 + ahalf * 32;

    int brow = tid >> 2, bu = tid & 3;
    uint32_t boff = (uint32_t)(brow * 80 + bu * 16);
    int bp = plist[brow];
    int bok = (bp >= 0) ? 16 : 0;
    const __nv_bfloat16* xh = g_hh + ((bp >= 0) ? (size_t)bp * H : 0) + kbase + bu * 8;
    const __nv_bfloat16* xl = g_hl + ((bp >= 0) ? (size_t)bp * H : 0) + kbase + bu * 8;

    float4 pv0 = *(const float4*)(wrow + 0);
    float4 pv1 = *(const float4*)(wrow + 4);
    float4 pv2 = *(const float4*)(wrow + 8);
    float4 pv3 = *(const float4*)(wrow + 12);

    float acc[8][4];
#pragma unroll
    for (int i = 0; i < 8; i++) { acc[i][0] = acc[i][1] = acc[i][2] = acc[i][3] = 0.f; }

    uint32_t a_addr = ah_s + (uint32_t)((wid * 16 + (lane & 15)) * 80 + (lane >> 4) * 16);
    int bmi = lane >> 3;
    uint32_t b_off = (uint32_t)(((bmi >> 1) * 8 + (lane & 7)) * 80 + (bmi & 1) * 16);

    cpa16z(bh_s + boff, xh, bok);
    cpa16z(bl_s + boff, xl, bok);
    CPCOMMIT();
    split16(AH, AL, aoff, pv0, pv1, pv2, pv3);
    {
        const float* nx = wrow + 32;
        pv0 = *(const float4*)(nx + 0); pv1 = *(const float4*)(nx + 4);
        pv2 = *(const float4*)(nx + 8); pv3 = *(const float4*)(nx + 12);
    }
    CPWAIT0();
    __syncthreads();

    const int NCH = (H / KHP) / 32;   // 24
    for (int ch = 0; ch < NCH; ch++) {
        int cur = ch & 1, nxt = cur ^ 1;
        if (ch + 1 < NCH) {
            int k1 = (ch + 1) * 32;
            cpa16z(bh_s + (uint32_t)(nxt * 5120) + boff, xh + k1, bok);
            cpa16z(bl_s + (uint32_t)(nxt * 5120) + boff, xl + k1, bok);
            CPCOMMIT();
        }
#pragma unroll
        for (int ks = 0; ks < 2; ks++) {
            uint32_t ahf[4], alf[4];
            ldsm4(ahf, a_addr + (uint32_t)(cur * 10240) + ks * 32);
            ldsm4(alf, a_addr + 20480u + (uint32_t)(cur * 10240) + ks * 32);
#pragma unroll
            for (int j = 0; j < 4; j++) {
                uint32_t bhf[4], blf[4];
                uint32_t badd = (uint32_t)(cur * 5120 + j * 16 * 80 + ks * 32) + b_off;
                ldsm4(bhf, bh_s + badd);
                ldsm4(blf, bl_s + badd);
                mma_bf16(acc[2 * j], ahf, bhf[0], bhf[1]);
                mma_bf16(acc[2 * j], ahf, blf[0], blf[1]);
                mma_bf16(acc[2 * j], alf, bhf[0], bhf[1]);
                mma_bf16(acc[2 * j + 1], ahf, bhf[2], bhf[3]);
                mma_bf16(acc[2 * j + 1], ahf, blf[2], blf[3]);
                mma_bf16(acc[2 * j + 1], alf, bhf[2], bhf[3]);
            }
        }
        if (ch + 1 < NCH) {
            split16(AH + nxt * 10240, AL + nxt * 10240, aoff, pv0, pv1, pv2, pv3);
            if (ch + 2 < NCH) {
                const float* nx = wrow + (ch + 2) * 32;
                pv0 = *(const float4*)(nx + 0); pv1 = *(const float4*)(nx + 4);
                pv2 = *(const float4*)(nx + 8); pv3 = *(const float4*)(nx + 12);
            }
            CPWAIT0();
        }
        __syncthreads();
    }
    int g = lane >> 2, t4 = lane & 3;
    int ddA = n0 + wid * 16 + g;
    int ddB = ddA + 8;
    float bA = (kpart == 0) ? b2[e * D + ddA] : 0.f;
    float bB = (kpart == 0) ? b2[e * D + ddB] : 0.f;
    float* yp = g_yp[kpart];
#pragma unroll
    for (int nf = 0; nf < 8; nf++) {
        int tok = nf * 8 + t4 * 2;
        if (tok < ctn) {
            int p = plist[tok];
            yp[(size_t)p * D + ddA] = acc[nf][0] + bA;
            yp[(size_t)p * D + ddB] = acc[nf][2] + bB;
        }
        if (tok + 1 < ctn) {
            int p = plist[tok + 1];
            yp[(size_t)p * D + ddA] = acc[nf][1] + bA;
            yp[(size_t)p * D + ddB] = acc[nf][3] + bB;
        }
    }
}

// ------------------------- kI: combine (sum KHP partials) -------------------
__global__ __launch_bounds__(256) void kI_combine(float* __restrict__ out_y)
{
    int tok = blockIdx.x;
    int tid = threadIdx.x;
    float w0 = g_topw[tok * 2], w1 = g_topw[tok * 2 + 1];
    size_t o0 = (size_t)(tok * 2) * D;
    size_t o1 = (size_t)(tok * 2 + 1) * D;
    for (int dd = tid; dd < D; dd += 256) {
        float y0 = 0.f, y1 = 0.f;
#pragma unroll
        for (int p = 0; p < KHP; p++) {
            y0 += g_yp[p][o0 + dd];
            y1 += g_yp[p][o1 + dd];
        }
        out_y[(size_t)tok * D + dd] += w0 * y0 + w1 * y1;
    }
}

// ------------------------- launch ------------------------------------------
extern "C" void kernel_launch(void* const* d_in, const int* in_sizes, int n_in,
                              void* d_out, int out_size)
{
    (void)in_sizes; (void)n_in; (void)out_size;
    const float* hidden = (const float*)d_in[0];
    const float* probe  = (const float*)d_in[1];
    const float* ipw    = (const float*)d_in[2];
    const float* ipb    = (const float*)d_in[3];
    const float* opw    = (const float*)d_in[4];
    const float* opb    = (const float*)d_in[5];
    const float* lnw    = (const float*)d_in[6];
    const float* lnb    = (const float*)d_in[7];
    const float* gw     = (const float*)d_in[8];
    const float* w1     = (const float*)d_in[9];
    const float* b1     = (const float*)d_in[10];
    const float* w2     = (const float*)d_in[11];
    const float* b2     = (const float*)d_in[12];
    float* out = (float*)d_out;

    cudaFuncSetAttribute(kB_scores_mma, cudaFuncAttributeMaxDynamicSharedMemorySize, KB_SMEM);
    cudaFuncSetAttribute(kD_pooled_mma, cudaFuncAttributeMaxDynamicSharedMemorySize, KD_SMEM);
    cudaFuncSetAttribute(kG_fc1_mma, cudaFuncAttributeMaxDynamicSharedMemorySize, GM_SMEM);
    cudaFuncSetAttribute(kH_fc2_mma, cudaFuncAttributeMaxDynamicSharedMemorySize, GM_SMEM);

    const int OFF_LOSS = B * T * D;        // 196608
    const int OFF_AW   = OFF_LOSS + 1;     // 196609

    kA_qtilde<<<NT, 256>>>(probe, ipw, ipb);
    kB_scores_mma<<<dim3(S / 128, B), 256, KB_SMEM>>>(hidden);
    kC_softmax<<<NTOK, 384>>>(out + OFF_AW);
    kD_pooled_mma<<<dim3(D / 128, B), 256, KD_SMEM>>>(hidden);
    kE1_vproj_mma<<<dim3(NH, 4), 256>>>(ipw, ipb);
    kE2_outproj<<<dim3(6, 8), 256>>>(opw, opb, out);
    kE3_ln_gate<<<NTOK, 256>>>(lnw, lnb, gw);
    kF_route<<<1, 256>>>(out + OFF_LOSS);
    kG_fc1_mma<<<dim3(H / 128, E, 4), 256, GM_SMEM>>>(w1, b1);
    kH_fc2_mma<<<dim3(D / 128, E, 4 * KHP), 256, GM_SMEM>>>(w2, b2);
    kI_combine<<<NTOK, 256>>>(out);
}